// round 12
// baseline (speedup 1.0000x reference)
#include <cuda_runtime.h>
#include <cuda_fp16.h>
#include <math.h>
#include <stdint.h>

#define BATCH   2
#define SEQ     2048
#define DMODEL  1024
#define NHEADS  16
#define HDIM    64
#define MROWS   (BATCH*SEQ)        // 4096
#define EDIM    (3*DMODEL)         // 3072
#define KD      DMODEL             // GEMM K = 1024
#define NK      (KD/32)            // 32 k-chunks of 32
#define BH      (BATCH*NHEADS)     // 32

// Scratch (device globals; no runtime allocation allowed)
__device__ __align__(128) __half g_abf[MROWS*KD];      // fp16 activations (h, then attn-out)
__device__ __align__(128) __half g_bbf[EDIM*KD];       // fp16 w_qkv
__device__ __align__(128) __half g_bbf2[DMODEL*KD];    // fp16 w_out
// head-major fp16 q/k/v: [sec: q, k, v][bh][t][d]
__device__ __align__(128) __half g_split[(size_t)3*BH*SEQ*HDIM];
#define SEC_ELEMS ((size_t)BH*SEQ*HDIM)

// ===========================================================================
// helpers
// ===========================================================================
__device__ __forceinline__ void pdl_wait() {
    asm volatile("griddepcontrol.wait;" ::: "memory");
}
__device__ __forceinline__ uint32_t smem_u32(const void* p) {
    uint32_t a;
    asm("{ .reg .u64 t; cvta.to.shared.u64 t, %1; cvt.u32.u64 %0, t; }" : "=r"(a) : "l"(p));
    return a;
}
__device__ __forceinline__ void cp16(uint32_t smem, const void* g) {
    asm volatile("cp.async.cg.shared.global [%0], [%1], 16;" :: "r"(smem), "l"(g) : "memory");
}
__device__ __forceinline__ void cp_commit() {
    asm volatile("cp.async.commit_group;" ::: "memory");
}
template<int N> __device__ __forceinline__ void cp_wait() {
    asm volatile("cp.async.wait_group %0;" :: "n"(N) : "memory");
}
__device__ __forceinline__ void ldsm4(uint32_t& r0, uint32_t& r1, uint32_t& r2, uint32_t& r3,
                                      uint32_t addr) {
    asm volatile("ldmatrix.sync.aligned.m8n8.x4.shared.b16 {%0,%1,%2,%3}, [%4];"
                 : "=r"(r0), "=r"(r1), "=r"(r2), "=r"(r3) : "r"(addr));
}
__device__ __forceinline__ void ldsm4t(uint32_t& r0, uint32_t& r1, uint32_t& r2, uint32_t& r3,
                                       uint32_t addr) {
    asm volatile("ldmatrix.sync.aligned.m8n8.x4.trans.shared.b16 {%0,%1,%2,%3}, [%4];"
                 : "=r"(r0), "=r"(r1), "=r"(r2), "=r"(r3) : "r"(addr));
}
__device__ __forceinline__ void mma16816(float* d, const uint32_t* a, const uint32_t* b) {
    asm volatile("mma.sync.aligned.m16n8k16.row.col.f32.f16.f16.f32 "
                 "{%0,%1,%2,%3}, {%4,%5,%6,%7}, {%8,%9}, {%0,%1,%2,%3};"
                 : "+f"(d[0]), "+f"(d[1]), "+f"(d[2]), "+f"(d[3])
                 : "r"(a[0]), "r"(a[1]), "r"(a[2]), "r"(a[3]), "r"(b[0]), "r"(b[1]));
}

// ===========================================================================
// K1: merged RMSNorm + weight conversion (independent halves of the grid).
// ===========================================================================
__global__ void prep_kernel(const float* __restrict__ x, const float* __restrict__ w,
                            const float* __restrict__ w_qkv, const float* __restrict__ w_out) {
    int tid = threadIdx.x;
    if (blockIdx.x < MROWS) {
        int row = blockIdx.x;
        float4 v = *(const float4*)(x + (size_t)row * DMODEL + tid * 4);
        float ss = v.x*v.x + v.y*v.y + v.z*v.z + v.w*v.w;
#pragma unroll
        for (int off = 16; off > 0; off >>= 1)
            ss += __shfl_xor_sync(0xffffffffu, ss, off);
        __shared__ float red[8];
        if ((tid & 31) == 0) red[tid >> 5] = ss;
        __syncthreads();
        float tot = red[0] + red[1] + red[2] + red[3]
                  + red[4] + red[5] + red[6] + red[7];
        float inv = rsqrtf(tot * (1.0f / DMODEL) + 1e-6f);
        float4 wv = *(const float4*)(w + tid * 4);
        __half2 h0 = __floats2half2_rn(v.x * inv * wv.x, v.y * inv * wv.y);
        __half2 h1 = __floats2half2_rn(v.z * inv * wv.z, v.w * inv * wv.w);
        uint2 pack = make_uint2(*(uint32_t*)&h0, *(uint32_t*)&h1);
        *(uint2*)(g_abf + (size_t)row * KD + tid * 4) = pack;
    } else {
        int idx = (blockIdx.x - MROWS) * 256 + tid;
        int e4 = idx * 4;
        float4 v;
        __half* dst;
        if (e4 < EDIM*DMODEL) {
            v = *(const float4*)(w_qkv + e4);
            dst = g_bbf + e4;
        } else {
            int j = e4 - EDIM*DMODEL;
            v = *(const float4*)(w_out + j);
            dst = g_bbf2 + j;
        }
        __half2 h0 = __floats2half2_rn(v.x, v.y);
        __half2 h1 = __floats2half2_rn(v.z, v.w);
        uint2 pack = make_uint2(*(uint32_t*)&h0, *(uint32_t*)&h1);
        *(uint2*)dst = pack;
    }
}

// ===========================================================================
// HMMA GEMM (fp16, K=1024). QKV=true: epilogue writes fp16 head-major into
// g_split. QKV=false: float C + residual.
// ===========================================================================
template<bool QKV>
__global__ __launch_bounds__(256) void gemm_mma_kernel(
    const __half* __restrict__ A, const __half* __restrict__ Bw,
    const float* __restrict__ Rsd, float* __restrict__ C, int N)
{
    __shared__ __align__(128) __half sA[2][128*40];
    __shared__ __align__(128) __half sB[2][128*40];

    pdl_wait();

    int tid = threadIdx.x, lid = tid & 31, wid = tid >> 5;
    int wm = (wid & 1) * 64;
    int wn = (wid >> 1) * 32;
    int m0 = blockIdx.y * 128, n0 = blockIdx.x * 128;

    int ldrow = tid >> 1;
    int ldcol = (tid & 1) * 32;       // bytes
    const char* gA = (const char*)(A  + (size_t)(m0 + ldrow) * KD) + ldcol;
    const char* gB = (const char*)(Bw + (size_t)(n0 + ldrow) * KD) + ldcol;

    auto prefetch = [&](int c) {
        int s = c & 1;
        uint32_t da = smem_u32(&sA[s][ldrow * 40]) + (uint32_t)ldcol;
        uint32_t db = smem_u32(&sB[s][ldrow * 40]) + (uint32_t)ldcol;
        const char* a = gA + (size_t)c * 64;
        const char* b = gB + (size_t)c * 64;
        cp16(da, a);      cp16(da + 16, a + 16);
        cp16(db, b);      cp16(db + 16, b + 16);
        cp_commit();
    };

    float acc[4][4][4] = {};

    prefetch(0); prefetch(1);

    int g  = lid >> 3, r8 = lid & 7;
    int a_m = wm + (g & 1) * 8 + r8;
    int a_k = (g >> 1) * 8;
    int b_n = wn + (g >> 1) * 8 + r8;
    int b_k = (g & 1) * 8;

    for (int kt = 0; kt < NK; kt++) {
        int s = kt & 1;
        if (kt + 1 < NK) cp_wait<1>(); else cp_wait<0>();
        __syncthreads();

        uint32_t baseA = smem_u32(&sA[s][0]);
        uint32_t baseB = smem_u32(&sB[s][0]);
#pragma unroll
        for (int ks = 0; ks < 2; ks++) {
            uint32_t a[4][4], b[4][2];
#pragma unroll
            for (int mt = 0; mt < 4; mt++) {
                uint32_t addr = baseA + (uint32_t)(a_m + mt*16) * 80u
                                      + (uint32_t)(a_k + ks*16) * 2u;
                ldsm4(a[mt][0], a[mt][1], a[mt][2], a[mt][3], addr);
            }
#pragma unroll
            for (int nt = 0; nt < 2; nt++) {
                uint32_t r0, r1, r2, r3;
                uint32_t addr = baseB + (uint32_t)(b_n + nt*16) * 80u
                                      + (uint32_t)(b_k + ks*16) * 2u;
                ldsm4(r0, r1, r2, r3, addr);
                b[nt*2][0] = r0;   b[nt*2][1] = r1;
                b[nt*2+1][0] = r2; b[nt*2+1][1] = r3;
            }
#pragma unroll
            for (int mt = 0; mt < 4; mt++)
#pragma unroll
                for (int nn = 0; nn < 4; nn++)
                    mma16816(acc[mt][nn], a[mt], b[nn]);
        }
        __syncthreads();
        if (kt + 2 < NK) prefetch(kt + 2);
    }

    int row = lid >> 2, col = (lid & 3) * 2;
#pragma unroll
    for (int mt = 0; mt < 4; mt++) {
#pragma unroll
        for (int nn = 0; nn < 4; nn++) {
            int m = m0 + wm + mt*16 + row;
            int n = n0 + wn + nn*8 + col;
            if (QKV) {
                int sc = n >> 10, h = (n >> 6) & 15, d = n & 63;
                int t = m & (SEQ - 1), bb = m >> 11;
                size_t base = (size_t)sc * SEC_ELEMS
                            + ((size_t)(bb * NHEADS + h) * SEQ + t) * HDIM + d;
                __half2 v0 = __floats2half2_rn(acc[mt][nn][0], acc[mt][nn][1]);
                __half2 v1 = __floats2half2_rn(acc[mt][nn][2], acc[mt][nn][3]);
                *(__half2*)(g_split + base)            = v0;
                *(__half2*)(g_split + base + 8*HDIM)   = v1;
            } else {
                float2 v0 = make_float2(acc[mt][nn][0], acc[mt][nn][1]);
                float2 v1 = make_float2(acc[mt][nn][2], acc[mt][nn][3]);
                float2 q0 = *(const float2*)(Rsd + (size_t)m * N + n);
                float2 q1 = *(const float2*)(Rsd + (size_t)(m+8) * N + n);
                v0.x += q0.x; v0.y += q0.y;
                v1.x += q1.x; v1.y += q1.y;
                *(float2*)(C + (size_t)m * N + n)     = v0;
                *(float2*)(C + (size_t)(m+8) * N + n) = v1;
            }
        }
    }
}

// ===========================================================================
// K3: in-place fp16 RoPE on Q,K sections of g_split.
// ===========================================================================
__global__ void rope_kernel() {
    pdl_wait();
    int idx = blockIdx.x * 256 + threadIdx.x;   // BH*2*SEQ*16
    int k  = idx & 15;
    int t  = (idx >> 4) & (SEQ - 1);
    int sc = (idx >> 15) & 1;                   // 0 = q, 1 = k
    int bh = idx >> 16;
    __half* p = g_split + (size_t)sc * SEC_ELEMS + ((size_t)bh * SEQ + t) * HDIM + 2*k;
    float2 a = __half22float2(*(__half2*)(p));
    float2 b = __half22float2(*(__half2*)(p + 32));
    const float NEG_L2_10K_32 = -0.41524101186092029f;   // -log2(10000)/32
    float if0 = exp2f((float)(2*k)   * NEG_L2_10K_32);
    float if1 = exp2f((float)(2*k+1) * NEG_L2_10K_32);
    float s0, c0, s1, c1;
    __sincosf((float)t * if0, &s0, &c0);
    __sincosf((float)t * if1, &s1, &c1);
    float y0 = a.x*c0 - b.x*s0, y1 = a.y*c1 - b.y*s1;
    float z0 = b.x*c0 + a.x*s0, z1 = b.y*c1 + a.y*s1;
    if (sc == 0) {
        const float QS = 0.125f * 1.4426950408889634f;   // 1/sqrt(64) * log2(e)
        y0 *= QS; y1 *= QS; z0 *= QS; z1 *= QS;
    }
    *(__half2*)(p)      = __floats2half2_rn(y0, y1);
    *(__half2*)(p + 32) = __floats2half2_rn(z0, z1);
}

// ===========================================================================
// K4: HMMA causal flash attention, software-pipelined S-MMA (1 tile ahead),
// 3-stage KV smem. fp16 operands, exp2-domain fp32 softmax.
// grid (SEQ/64, NHEADS, BATCH), 128 threads. Heavy-first.
// ===========================================================================
#define ATS 72                         // smem row stride in halfs
#define AT_TILE (64*ATS)               // one 64x64 array
#define ATT_SMEM ((1 + 6) * AT_TILE * 2)   // Q + 3 stages x (K,V) = 64512 B

__global__ __launch_bounds__(128, 3) void attn_mma_kernel() {
    extern __shared__ __half sh[];
    __half* Qh = sh;
    __half* KV = sh + AT_TILE;   // stage s (0..2): +s*2*AT_TILE; [Kh, Vh]

    pdl_wait();

    int qt = (gridDim.x - 1) - blockIdx.x;      // heavy CTAs first
    int hh = blockIdx.y, b = blockIdx.z;
    int bh = b * NHEADS + hh;
    int tid = threadIdx.x;
    int lid = tid & 31, wid = tid >> 5;
    int q0 = qt * 64;

    const __half* gq = g_split + 0*SEC_ELEMS + (size_t)bh * SEQ * HDIM;
    const __half* gk = g_split + 1*SEC_ELEMS + (size_t)bh * SEQ * HDIM;
    const __half* gv = g_split + 2*SEC_ELEMS + (size_t)bh * SEQ * HDIM;

    int ldrow = tid >> 1;          // 0..63
    int ldh   = (tid & 1) * 32;    // halfs offset within row

    // Q load (joins group of prefetch(0))
    {
        const __half* s0 = gq + (size_t)(q0 + ldrow) * HDIM + ldh;
        uint32_t d0 = smem_u32(Qh + ldrow * ATS + ldh);
#pragma unroll
        for (int i = 0; i < 4; i++) cp16(d0 + i*16, s0 + i*8);
    }

    auto prefetch = [&](int kt) {
        int s = kt % 3;
        __half* base = KV + s * 2 * AT_TILE;
        size_t gr = (size_t)(kt * 64 + ldrow) * HDIM + ldh;
        const __half* srcs[2] = { gk + gr, gv + gr };
#pragma unroll
        for (int a = 0; a < 2; a++) {
            uint32_t dst = smem_u32(base + a * AT_TILE + ldrow * ATS + ldh);
#pragma unroll
            for (int i = 0; i < 4; i++) cp16(dst + i*16, srcs[a] + i*8);
        }
        cp_commit();
    };

    prefetch(0);                       // group: Q + KV0
    if (qt >= 1) { prefetch(1); cp_wait<1>(); } else { cp_wait<0>(); }
    __syncthreads();                   // tile 0 (and Q) visible

    int g  = lid >> 3, r8 = lid & 7;
    int a_row = wid * 16 + (g & 1) * 8 + r8;   // Q smem row
    int a_kof = (g >> 1) * 8;                  // + kc*16
    int b_row = (g >> 1) * 8 + r8;             // K smem row within 16-pair (+p*16)
    int b_kof = (g & 1) * 8;
    int v_row = lid & 15;                      // + kc*16
    int v_col = (lid >> 4) * 8;                // + p*16
    int qrow_loc = wid * 16 + (lid >> 2);      // local q row for c0/c1

    // ---- hoist Q fragments (loop-invariant) ----
    uint32_t aq[4][4];
    {
        uint32_t bQh = smem_u32(Qh);
#pragma unroll
        for (int kc = 0; kc < 4; kc++) {
            uint32_t aoff = (uint32_t)(a_row * ATS + kc*16 + a_kof) * 2u;
            ldsm4(aq[kc][0], aq[kc][1], aq[kc][2], aq[kc][3], bQh + aoff);
        }
    }

    float m0 = -1e30f, m1 = -1e30f, l0 = 0.f, l1 = 0.f;
    float oacc[8][4] = {};
    float sacc[8][4];

    // ---- issue S for a tile (reads K stage tile%3) ----
    auto issue_S = [&](int tile, float (*sa)[4]) {
        uint32_t bKh = smem_u32(KV + (tile % 3) * 2 * AT_TILE);
#pragma unroll
        for (int j = 0; j < 8; j++)
#pragma unroll
            for (int c = 0; c < 4; c++) sa[j][c] = 0.f;
#pragma unroll
        for (int kc = 0; kc < 4; kc++) {
            uint32_t bhf[8][2];
#pragma unroll
            for (int p = 0; p < 4; p++) {
                uint32_t boff = (uint32_t)((p*16 + b_row) * ATS + kc*16 + b_kof) * 2u;
                uint32_t r0, r1, r2, r3;
                ldsm4(r0, r1, r2, r3, bKh + boff);
                bhf[2*p][0] = r0; bhf[2*p][1] = r1;
                bhf[2*p+1][0] = r2; bhf[2*p+1][1] = r3;
            }
#pragma unroll
            for (int j = 0; j < 8; j++)
                mma16816(sa[j], aq[kc], bhf[j]);
        }
    };

    issue_S(0, sacc);   // S(0); consumed at kt=0 (latency exposed once only)

    for (int kt = 0; kt <= qt; kt++) {
        // ---- a: mask + softmax on S(kt) (issued >= one phase earlier) ----
        if (kt == qt) {
#pragma unroll
            for (int j = 0; j < 8; j++) {
                int col = j*8 + (lid & 3) * 2;
                if (col     > qrow_loc)     sacc[j][0] = -1e30f;
                if (col + 1 > qrow_loc)     sacc[j][1] = -1e30f;
                if (col     > qrow_loc + 8) sacc[j][2] = -1e30f;
                if (col + 1 > qrow_loc + 8) sacc[j][3] = -1e30f;
            }
        }
        float mx0 = -1e30f, mx1 = -1e30f;
#pragma unroll
        for (int j = 0; j < 8; j++) {
            mx0 = fmaxf(mx0, fmaxf(sacc[j][0], sacc[j][1]));
            mx1 = fmaxf(mx1, fmaxf(sacc[j][2], sacc[j][3]));
        }
        mx0 = fmaxf(mx0, __shfl_xor_sync(0xffffffffu, mx0, 1));
        mx0 = fmaxf(mx0, __shfl_xor_sync(0xffffffffu, mx0, 2));
        mx1 = fmaxf(mx1, __shfl_xor_sync(0xffffffffu, mx1, 1));
        mx1 = fmaxf(mx1, __shfl_xor_sync(0xffffffffu, mx1, 2));
        float mn0 = fmaxf(m0, mx0), mn1 = fmaxf(m1, mx1);
        float al0 = exp2f(m0 - mn0), al1 = exp2f(m1 - mn1);
        float s0 = 0.f, s1 = 0.f;
#pragma unroll
        for (int j = 0; j < 8; j++) {
            sacc[j][0] = exp2f(sacc[j][0] - mn0);
            sacc[j][1] = exp2f(sacc[j][1] - mn0);
            sacc[j][2] = exp2f(sacc[j][2] - mn1);
            sacc[j][3] = exp2f(sacc[j][3] - mn1);
            s0 += sacc[j][0] + sacc[j][1];
            s1 += sacc[j][2] + sacc[j][3];
        }
        s0 += __shfl_xor_sync(0xffffffffu, s0, 1);
        s0 += __shfl_xor_sync(0xffffffffu, s0, 2);
        s1 += __shfl_xor_sync(0xffffffffu, s1, 1);
        s1 += __shfl_xor_sync(0xffffffffu, s1, 2);
        l0 = l0 * al0 + s0;  l1 = l1 * al1 + s1;
        m0 = mn0;  m1 = mn1;
#pragma unroll
        for (int j = 0; j < 8; j++) {
            oacc[j][0] *= al0; oacc[j][1] *= al0;
            oacc[j][2] *= al1; oacc[j][3] *= al1;
        }

        // ---- P fragments (fp16); sacc is dead after this ----
        uint32_t ph01[8], ph23[8];
#pragma unroll
        for (int j = 0; j < 8; j++) {
            __half2 t0 = __floats2half2_rn(sacc[j][0], sacc[j][1]);
            __half2 t1 = __floats2half2_rn(sacc[j][2], sacc[j][3]);
            ph01[j] = *(uint32_t*)&t0;
            ph23[j] = *(uint32_t*)&t1;
        }

        // ---- b/c: wait for tile kt+1, then issue S(kt+1) into sacc ----
        if (kt < qt) {
            if (kt + 2 <= qt) { prefetch(kt + 2); cp_wait<1>(); } else { cp_wait<0>(); }
            __syncthreads();
            issue_S(kt + 1, sacc);
        }

        // ---- d: O += P V(kt), V via ldmatrix.trans (stage kt%3) ----
        uint32_t bVh = smem_u32(KV + (kt % 3) * 2 * AT_TILE) + AT_TILE * 2;
#pragma unroll
        for (int kc = 0; kc < 4; kc++) {
            uint32_t aH[4] = { ph01[2*kc], ph23[2*kc], ph01[2*kc+1], ph23[2*kc+1] };
#pragma unroll
            for (int p = 0; p < 4; p++) {
                uint32_t voff = (uint32_t)((kc*16 + v_row) * ATS + p*16 + v_col) * 2u;
                uint32_t h0, h1, h2, h3;
                ldsm4t(h0, h1, h2, h3, bVh + voff);
                uint32_t bv0[2] = { h0, h1 }, bv1[2] = { h2, h3 };
                mma16816(oacc[2*p],   aH, bv0);
                mma16816(oacc[2*p+1], aH, bv1);
            }
        }

        // ---- e: end-of-iter barrier (protects next prefetch overwrite) ----
        if (kt < qt) __syncthreads();
    }

    // ---- epilogue: normalize, write fp16 into g_abf ----
    float inv0 = 1.0f / l0, inv1 = 1.0f / l1;
    int mg0 = b * SEQ + q0 + qrow_loc;
    int mg1 = mg0 + 8;
#pragma unroll
    for (int j = 0; j < 8; j++) {
        int col = hh * HDIM + j*8 + (lid & 3) * 2;
        __half2 hp0 = __floats2half2_rn(oacc[j][0] * inv0, oacc[j][1] * inv0);
        __half2 hp1 = __floats2half2_rn(oacc[j][2] * inv1, oacc[j][3] * inv1);
        *(__half2*)(g_abf + (size_t)mg0 * KD + col) = hp0;
        *(__half2*)(g_abf + (size_t)mg1 * KD + col) = hp1;
    }
}

// ===========================================================================
extern "C" void kernel_launch(void* const* d_in, const int* in_sizes, int n_in,
                              void* d_out, int out_size) {
    const float* x      = (const float*)d_in[0];
    const float* norm_w = (const float*)d_in[1];
    const float* w_qkv  = (const float*)d_in[2];
    const float* w_out  = (const float*)d_in[3];
    float* out = (float*)d_out;

    __half *p_abf, *p_bbf, *p_bbf2;
    cudaGetSymbolAddress((void**)&p_abf,  g_abf);
    cudaGetSymbolAddress((void**)&p_bbf,  g_bbf);
    cudaGetSymbolAddress((void**)&p_bbf2, g_bbf2);

    cudaFuncSetAttribute(attn_mma_kernel,
                         cudaFuncAttributeMaxDynamicSharedMemorySize, ATT_SMEM);

    cudaLaunchAttribute pdl[1];
    pdl[0].id = cudaLaunchAttributeProgrammaticStreamSerialization;
    pdl[0].val.programmaticStreamSerializationAllowed = 1;

    // 1. merged RMSNorm + weight convert
    prep_kernel<<<MROWS + ((EDIM+DMODEL)*DMODEL)/(256*4), 256>>>(x, norm_w, w_qkv, w_out);

    // 2. QKV projection
    {
        cudaLaunchConfig_t cfg = {};
        cfg.gridDim = dim3(EDIM/128, MROWS/128);
        cfg.blockDim = dim3(256);
        cfg.attrs = pdl; cfg.numAttrs = 1;
        cudaLaunchKernelEx(&cfg, gemm_mma_kernel<true>,
                           (const __half*)p_abf, (const __half*)p_bbf,
                           (const float*)nullptr, (float*)nullptr, (int)EDIM);
    }

    // 3. RoPE
    {
        cudaLaunchConfig_t cfg = {};
        cfg.gridDim = dim3((BH * 2 * SEQ * 16) / 256);
        cfg.blockDim = dim3(256);
        cfg.attrs = pdl; cfg.numAttrs = 1;
        cudaLaunchKernelEx(&cfg, rope_kernel);
    }

    // 4. attention (pipelined S-MMA)
    {
        cudaLaunchConfig_t cfg = {};
        cfg.gridDim = dim3(SEQ/64, NHEADS, BATCH);
        cfg.blockDim = dim3(128);
        cfg.dynamicSmemBytes = ATT_SMEM;
        cfg.attrs = pdl; cfg.numAttrs = 1;
        cudaLaunchKernelEx(&cfg, attn_mma_kernel);
    }

    // 5. Output projection + residual
    {
        cudaLaunchConfig_t cfg = {};
        cfg.gridDim = dim3(DMODEL/128, MROWS/128);
        cfg.blockDim = dim3(256);
        cfg.attrs = pdl; cfg.numAttrs = 1;
        cudaLaunchKernelEx(&cfg, gemm_mma_kernel<false>,
                           (const __half*)p_abf, (const __half*)p_bbf2,
                           (const float*)x, (float*)out, (int)DMODEL);
    }
}

// round 14
// speedup vs baseline: 1.0465x; 1.0465x over previous
#include <cuda_runtime.h>
#include <cuda_fp16.h>
#include <math.h>
#include <stdint.h>

#define BATCH   2
#define SEQ     2048
#define DMODEL  1024
#define NHEADS  16
#define HDIM    64
#define MROWS   (BATCH*SEQ)        // 4096
#define EDIM    (3*DMODEL)         // 3072
#define KD      DMODEL             // GEMM K = 1024
#define NK      (KD/32)            // 32 k-chunks of 32
#define BH      (BATCH*NHEADS)     // 32

// Scratch (device globals; no runtime allocation allowed)
__device__ __align__(128) __half g_abf[MROWS*KD];      // fp16 activations (h, then attn-out)
__device__ __align__(128) __half g_bbf[EDIM*KD];       // fp16 w_qkv
__device__ __align__(128) __half g_bbf2[DMODEL*KD];    // fp16 w_out
// head-major fp16 q/k/v: [sec: q, k, v][bh][t][d]
__device__ __align__(128) __half g_split[(size_t)3*BH*SEQ*HDIM];
#define SEC_ELEMS ((size_t)BH*SEQ*HDIM)

// ===========================================================================
// helpers
// ===========================================================================
__device__ __forceinline__ void pdl_wait() {
    asm volatile("griddepcontrol.wait;" ::: "memory");
}
__device__ __forceinline__ uint32_t smem_u32(const void* p) {
    uint32_t a;
    asm("{ .reg .u64 t; cvta.to.shared.u64 t, %1; cvt.u32.u64 %0, t; }" : "=r"(a) : "l"(p));
    return a;
}
__device__ __forceinline__ void cp16(uint32_t smem, const void* g) {
    asm volatile("cp.async.cg.shared.global [%0], [%1], 16;" :: "r"(smem), "l"(g) : "memory");
}
__device__ __forceinline__ void cp_commit() {
    asm volatile("cp.async.commit_group;" ::: "memory");
}
template<int N> __device__ __forceinline__ void cp_wait() {
    asm volatile("cp.async.wait_group %0;" :: "n"(N) : "memory");
}
__device__ __forceinline__ void ldsm4(uint32_t& r0, uint32_t& r1, uint32_t& r2, uint32_t& r3,
                                      uint32_t addr) {
    asm volatile("ldmatrix.sync.aligned.m8n8.x4.shared.b16 {%0,%1,%2,%3}, [%4];"
                 : "=r"(r0), "=r"(r1), "=r"(r2), "=r"(r3) : "r"(addr));
}
__device__ __forceinline__ void ldsm4t(uint32_t& r0, uint32_t& r1, uint32_t& r2, uint32_t& r3,
                                       uint32_t addr) {
    asm volatile("ldmatrix.sync.aligned.m8n8.x4.trans.shared.b16 {%0,%1,%2,%3}, [%4];"
                 : "=r"(r0), "=r"(r1), "=r"(r2), "=r"(r3) : "r"(addr));
}
__device__ __forceinline__ void mma16816(float* d, const uint32_t* a, const uint32_t* b) {
    asm volatile("mma.sync.aligned.m16n8k16.row.col.f32.f16.f16.f32 "
                 "{%0,%1,%2,%3}, {%4,%5,%6,%7}, {%8,%9}, {%0,%1,%2,%3};"
                 : "+f"(d[0]), "+f"(d[1]), "+f"(d[2]), "+f"(d[3])
                 : "r"(a[0]), "r"(a[1]), "r"(a[2]), "r"(a[3]), "r"(b[0]), "r"(b[1]));
}
__device__ __forceinline__ uint32_t pack_f16(float a, float b) {
    __half2 t = __floats2half2_rn(a, b);
    return *(uint32_t*)&t;
}
// SW128 swizzle on a byte offset within a 64x128B tile (16B-aligned preserved)
__device__ __forceinline__ uint32_t swz(uint32_t off) {
    return off ^ ((off >> 3) & 0x70);
}

// ===========================================================================
// K1: merged RMSNorm + weight conversion (independent halves of the grid).
// ===========================================================================
__global__ void prep_kernel(const float* __restrict__ x, const float* __restrict__ w,
                            const float* __restrict__ w_qkv, const float* __restrict__ w_out) {
    int tid = threadIdx.x;
    if (blockIdx.x < MROWS) {
        int row = blockIdx.x;
        float4 v = *(const float4*)(x + (size_t)row * DMODEL + tid * 4);
        float ss = v.x*v.x + v.y*v.y + v.z*v.z + v.w*v.w;
#pragma unroll
        for (int off = 16; off > 0; off >>= 1)
            ss += __shfl_xor_sync(0xffffffffu, ss, off);
        __shared__ float red[8];
        if ((tid & 31) == 0) red[tid >> 5] = ss;
        __syncthreads();
        float tot = red[0] + red[1] + red[2] + red[3]
                  + red[4] + red[5] + red[6] + red[7];
        float inv = rsqrtf(tot * (1.0f / DMODEL) + 1e-6f);
        float4 wv = *(const float4*)(w + tid * 4);
        __half2 h0 = __floats2half2_rn(v.x * inv * wv.x, v.y * inv * wv.y);
        __half2 h1 = __floats2half2_rn(v.z * inv * wv.z, v.w * inv * wv.w);
        uint2 pack = make_uint2(*(uint32_t*)&h0, *(uint32_t*)&h1);
        *(uint2*)(g_abf + (size_t)row * KD + tid * 4) = pack;
    } else {
        int idx = (blockIdx.x - MROWS) * 256 + tid;
        int e4 = idx * 4;
        float4 v;
        __half* dst;
        if (e4 < EDIM*DMODEL) {
            v = *(const float4*)(w_qkv + e4);
            dst = g_bbf + e4;
        } else {
            int j = e4 - EDIM*DMODEL;
            v = *(const float4*)(w_out + j);
            dst = g_bbf2 + j;
        }
        __half2 h0 = __floats2half2_rn(v.x, v.y);
        __half2 h1 = __floats2half2_rn(v.z, v.w);
        uint2 pack = make_uint2(*(uint32_t*)&h0, *(uint32_t*)&h1);
        *(uint2*)dst = pack;
    }
}

// ===========================================================================
// HMMA GEMM (fp16, K=1024). QKV=true: epilogue writes fp16 head-major into
// g_split. QKV=false: float C + residual.
// ===========================================================================
template<bool QKV>
__global__ __launch_bounds__(256) void gemm_mma_kernel(
    const __half* __restrict__ A, const __half* __restrict__ Bw,
    const float* __restrict__ Rsd, float* __restrict__ C, int N)
{
    __shared__ __align__(128) __half sA[2][128*40];
    __shared__ __align__(128) __half sB[2][128*40];

    pdl_wait();

    int tid = threadIdx.x, lid = tid & 31, wid = tid >> 5;
    int wm = (wid & 1) * 64;
    int wn = (wid >> 1) * 32;
    int m0 = blockIdx.y * 128, n0 = blockIdx.x * 128;

    int ldrow = tid >> 1;
    int ldcol = (tid & 1) * 32;       // bytes
    const char* gA = (const char*)(A  + (size_t)(m0 + ldrow) * KD) + ldcol;
    const char* gB = (const char*)(Bw + (size_t)(n0 + ldrow) * KD) + ldcol;

    auto prefetch = [&](int c) {
        int s = c & 1;
        uint32_t da = smem_u32(&sA[s][ldrow * 40]) + (uint32_t)ldcol;
        uint32_t db = smem_u32(&sB[s][ldrow * 40]) + (uint32_t)ldcol;
        const char* a = gA + (size_t)c * 64;
        const char* b = gB + (size_t)c * 64;
        cp16(da, a);      cp16(da + 16, a + 16);
        cp16(db, b);      cp16(db + 16, b + 16);
        cp_commit();
    };

    float acc[4][4][4] = {};

    prefetch(0); prefetch(1);

    int g  = lid >> 3, r8 = lid & 7;
    int a_m = wm + (g & 1) * 8 + r8;
    int a_k = (g >> 1) * 8;
    int b_n = wn + (g >> 1) * 8 + r8;
    int b_k = (g & 1) * 8;

    for (int kt = 0; kt < NK; kt++) {
        int s = kt & 1;
        if (kt + 1 < NK) cp_wait<1>(); else cp_wait<0>();
        __syncthreads();

        uint32_t baseA = smem_u32(&sA[s][0]);
        uint32_t baseB = smem_u32(&sB[s][0]);
#pragma unroll
        for (int ks = 0; ks < 2; ks++) {
            uint32_t a[4][4], b[4][2];
#pragma unroll
            for (int mt = 0; mt < 4; mt++) {
                uint32_t addr = baseA + (uint32_t)(a_m + mt*16) * 80u
                                      + (uint32_t)(a_k + ks*16) * 2u;
                ldsm4(a[mt][0], a[mt][1], a[mt][2], a[mt][3], addr);
            }
#pragma unroll
            for (int nt = 0; nt < 2; nt++) {
                uint32_t r0, r1, r2, r3;
                uint32_t addr = baseB + (uint32_t)(b_n + nt*16) * 80u
                                      + (uint32_t)(b_k + ks*16) * 2u;
                ldsm4(r0, r1, r2, r3, addr);
                b[nt*2][0] = r0;   b[nt*2][1] = r1;
                b[nt*2+1][0] = r2; b[nt*2+1][1] = r3;
            }
#pragma unroll
            for (int mt = 0; mt < 4; mt++)
#pragma unroll
                for (int nn = 0; nn < 4; nn++)
                    mma16816(acc[mt][nn], a[mt], b[nn]);
        }
        __syncthreads();
        if (kt + 2 < NK) prefetch(kt + 2);
    }

    int row = lid >> 2, col = (lid & 3) * 2;
#pragma unroll
    for (int mt = 0; mt < 4; mt++) {
#pragma unroll
        for (int nn = 0; nn < 4; nn++) {
            int m = m0 + wm + mt*16 + row;
            int n = n0 + wn + nn*8 + col;
            if (QKV) {
                int sc = n >> 10, h = (n >> 6) & 15, d = n & 63;
                int t = m & (SEQ - 1), bb = m >> 11;
                size_t base = (size_t)sc * SEC_ELEMS
                            + ((size_t)(bb * NHEADS + h) * SEQ + t) * HDIM + d;
                __half2 v0 = __floats2half2_rn(acc[mt][nn][0], acc[mt][nn][1]);
                __half2 v1 = __floats2half2_rn(acc[mt][nn][2], acc[mt][nn][3]);
                *(__half2*)(g_split + base)            = v0;
                *(__half2*)(g_split + base + 8*HDIM)   = v1;
            } else {
                float2 v0 = make_float2(acc[mt][nn][0], acc[mt][nn][1]);
                float2 v1 = make_float2(acc[mt][nn][2], acc[mt][nn][3]);
                float2 q0 = *(const float2*)(Rsd + (size_t)m * N + n);
                float2 q1 = *(const float2*)(Rsd + (size_t)(m+8) * N + n);
                v0.x += q0.x; v0.y += q0.y;
                v1.x += q1.x; v1.y += q1.y;
                *(float2*)(C + (size_t)m * N + n)     = v0;
                *(float2*)(C + (size_t)(m+8) * N + n) = v1;
            }
        }
    }
}

// ===========================================================================
// K3: in-place fp16 RoPE on Q,K sections of g_split.
// ===========================================================================
__global__ void rope_kernel() {
    pdl_wait();
    int idx = blockIdx.x * 256 + threadIdx.x;   // BH*2*SEQ*16
    int k  = idx & 15;
    int t  = (idx >> 4) & (SEQ - 1);
    int sc = (idx >> 15) & 1;                   // 0 = q, 1 = k
    int bh = idx >> 16;
    __half* p = g_split + (size_t)sc * SEC_ELEMS + ((size_t)bh * SEQ + t) * HDIM + 2*k;
    float2 a = __half22float2(*(__half2*)(p));
    float2 b = __half22float2(*(__half2*)(p + 32));
    const float NEG_L2_10K_32 = -0.41524101186092029f;   // -log2(10000)/32
    float if0 = exp2f((float)(2*k)   * NEG_L2_10K_32);
    float if1 = exp2f((float)(2*k+1) * NEG_L2_10K_32);
    float s0, c0, s1, c1;
    __sincosf((float)t * if0, &s0, &c0);
    __sincosf((float)t * if1, &s1, &c1);
    float y0 = a.x*c0 - b.x*s0, y1 = a.y*c1 - b.y*s1;
    float z0 = b.x*c0 + a.x*s0, z1 = b.y*c1 + a.y*s1;
    if (sc == 0) {
        const float QS = 0.125f * 1.4426950408889634f;   // 1/sqrt(64) * log2(e)
        y0 *= QS; y1 *= QS; z0 *= QS; z1 *= QS;
    }
    *(__half2*)(p)      = __floats2half2_rn(y0, y1);
    *(__half2*)(p + 32) = __floats2half2_rn(z0, z1);
}

// ===========================================================================
// K4: HMMA causal flash attention, SW128-swizzled stride-64 smem tiles
// (8KB each; Q + 2x(K,V) = 40960 B -> 5 CTAs/SM). r11 loop order,
// no Q hoist, inline P packing. Heavy-first, exp2 softmax.
// ===========================================================================
#define TILE_B 8192                      // one 64x64 fp16 tile, swizzled
#define ATT_SMEM (5 * TILE_B)            // 40960 bytes

__global__ __launch_bounds__(128, 5) void attn_mma_kernel() {
    extern __shared__ __half sh[];
    uint32_t bQ = smem_u32(sh);          // Q tile at offset 0
    // KV stage s (0..1): K at bQ + (1 + s*2)*TILE_B, V at +TILE_B more

    pdl_wait();

    int qt = (gridDim.x - 1) - blockIdx.x;      // heavy CTAs first
    int hh = blockIdx.y, b = blockIdx.z;
    int bh = b * NHEADS + hh;
    int tid = threadIdx.x;
    int lid = tid & 31, wid = tid >> 5;
    int q0 = qt * 64;

    const __half* gq = g_split + 0*SEC_ELEMS + (size_t)bh * SEQ * HDIM;
    const __half* gk = g_split + 1*SEC_ELEMS + (size_t)bh * SEQ * HDIM;
    const __half* gv = g_split + 2*SEC_ELEMS + (size_t)bh * SEQ * HDIM;

    int ldrow = tid >> 1;          // 0..63
    int ldh   = (tid & 1) * 32;    // halfs offset within row (0 or 32 -> 64B)

    // Q load (joins group of prefetch(0)); swizzled stores
    {
        const __half* s0 = gq + (size_t)(q0 + ldrow) * HDIM + ldh;
#pragma unroll
        for (int i = 0; i < 4; i++) {
            uint32_t off = (uint32_t)ldrow * 128u + (uint32_t)ldh * 2u + i * 16u;
            cp16(bQ + swz(off), s0 + i*8);
        }
    }

    auto prefetch = [&](int kt) {
        int s = kt & 1;
        uint32_t baseK = bQ + (1 + s*2) * TILE_B;
        size_t gr = (size_t)(kt * 64 + ldrow) * HDIM + ldh;
        const __half* srcs[2] = { gk + gr, gv + gr };
#pragma unroll
        for (int a = 0; a < 2; a++) {
            uint32_t base = baseK + a * TILE_B;
#pragma unroll
            for (int i = 0; i < 4; i++) {
                uint32_t off = (uint32_t)ldrow * 128u + (uint32_t)ldh * 2u + i * 16u;
                cp16(base + swz(off), srcs[a] + i*8);
            }
        }
        cp_commit();
    };
    prefetch(0);                      // group 0 = Q + tile 0
    if (qt > 0) { prefetch(1); cp_wait<1>(); } else { cp_wait<0>(); }
    __syncthreads();

    int g  = lid >> 3, r8 = lid & 7;
    int a_row = wid * 16 + (g & 1) * 8 + r8;   // Q smem row
    int a_kb  = ((g >> 1) * 8) * 2;            // byte offset within row (+kc*32)
    int b_row = (g >> 1) * 8 + r8;             // K smem row within 16-pair (+p*16)
    int b_kb  = ((g & 1) * 8) * 2;
    int v_row = lid & 15;                      // + kc*16
    int v_cb  = ((lid >> 4) * 8) * 2;          // byte offset within row (+p*32)
    int qrow_loc = wid * 16 + (lid >> 2);      // local q row for c0/c1

    float m0 = -1e30f, m1 = -1e30f, l0 = 0.f, l1 = 0.f;
    float oacc[8][4] = {};

    for (int kt = 0; kt <= qt; kt++) {
        uint32_t bKh = bQ + (1 + (kt & 1)*2) * TILE_B;
        uint32_t bVh = bKh + TILE_B;

        // ---- S = Q K^T (swizzled ldsm addresses) ----
        float sacc[8][4] = {};
#pragma unroll
        for (int kc = 0; kc < 4; kc++) {
            uint32_t ah[4];
            {
                uint32_t off = (uint32_t)a_row * 128u + (uint32_t)(kc*32 + a_kb);
                ldsm4(ah[0], ah[1], ah[2], ah[3], bQ + swz(off));
            }
            uint32_t bhf[8][2];
#pragma unroll
            for (int p = 0; p < 4; p++) {
                uint32_t off = (uint32_t)(p*16 + b_row) * 128u + (uint32_t)(kc*32 + b_kb);
                uint32_t r0, r1, r2, r3;
                ldsm4(r0, r1, r2, r3, bKh + swz(off));
                bhf[2*p][0] = r0; bhf[2*p][1] = r1;
                bhf[2*p+1][0] = r2; bhf[2*p+1][1] = r3;
            }
#pragma unroll
            for (int j = 0; j < 8; j++)
                mma16816(sacc[j], ah, bhf[j]);
        }

        // ---- causal mask on diagonal tile ----
        if (kt == qt) {
#pragma unroll
            for (int j = 0; j < 8; j++) {
                int col = j*8 + (lid & 3) * 2;
                if (col     > qrow_loc)     sacc[j][0] = -1e30f;
                if (col + 1 > qrow_loc)     sacc[j][1] = -1e30f;
                if (col     > qrow_loc + 8) sacc[j][2] = -1e30f;
                if (col + 1 > qrow_loc + 8) sacc[j][3] = -1e30f;
            }
        }

        // ---- online softmax (exp2 domain), rows qrow_loc and +8 ----
        float mx0 = -1e30f, mx1 = -1e30f;
#pragma unroll
        for (int j = 0; j < 8; j++) {
            mx0 = fmaxf(mx0, fmaxf(sacc[j][0], sacc[j][1]));
            mx1 = fmaxf(mx1, fmaxf(sacc[j][2], sacc[j][3]));
        }
        mx0 = fmaxf(mx0, __shfl_xor_sync(0xffffffffu, mx0, 1));
        mx0 = fmaxf(mx0, __shfl_xor_sync(0xffffffffu, mx0, 2));
        mx1 = fmaxf(mx1, __shfl_xor_sync(0xffffffffu, mx1, 1));
        mx1 = fmaxf(mx1, __shfl_xor_sync(0xffffffffu, mx1, 2));
        float mn0 = fmaxf(m0, mx0), mn1 = fmaxf(m1, mx1);
        float al0 = exp2f(m0 - mn0), al1 = exp2f(m1 - mn1);
        float s0 = 0.f, s1 = 0.f;
#pragma unroll
        for (int j = 0; j < 8; j++) {
            sacc[j][0] = exp2f(sacc[j][0] - mn0);
            sacc[j][1] = exp2f(sacc[j][1] - mn0);
            sacc[j][2] = exp2f(sacc[j][2] - mn1);
            sacc[j][3] = exp2f(sacc[j][3] - mn1);
            s0 += sacc[j][0] + sacc[j][1];
            s1 += sacc[j][2] + sacc[j][3];
        }
        s0 += __shfl_xor_sync(0xffffffffu, s0, 1);
        s0 += __shfl_xor_sync(0xffffffffu, s0, 2);
        s1 += __shfl_xor_sync(0xffffffffu, s1, 1);
        s1 += __shfl_xor_sync(0xffffffffu, s1, 2);
        l0 = l0 * al0 + s0;  l1 = l1 * al1 + s1;
        m0 = mn0;  m1 = mn1;
#pragma unroll
        for (int j = 0; j < 8; j++) {
            oacc[j][0] *= al0; oacc[j][1] *= al0;
            oacc[j][2] *= al1; oacc[j][3] *= al1;
        }

        // ---- O += P V: P packed inline per kc; V swizzled ldsm4t ----
#pragma unroll
        for (int kc = 0; kc < 4; kc++) {
            uint32_t aH[4];
            aH[0] = pack_f16(sacc[2*kc][0],   sacc[2*kc][1]);
            aH[1] = pack_f16(sacc[2*kc][2],   sacc[2*kc][3]);
            aH[2] = pack_f16(sacc[2*kc+1][0], sacc[2*kc+1][1]);
            aH[3] = pack_f16(sacc[2*kc+1][2], sacc[2*kc+1][3]);
#pragma unroll
            for (int p = 0; p < 4; p++) {
                uint32_t off = (uint32_t)(kc*16 + v_row) * 128u + (uint32_t)(p*32 + v_cb);
                uint32_t h0, h1, h2, h3;
                ldsm4t(h0, h1, h2, h3, bVh + swz(off));
                uint32_t bv0[2] = { h0, h1 }, bv1[2] = { h2, h3 };
                mma16816(oacc[2*p],   aH, bv0);
                mma16816(oacc[2*p+1], aH, bv1);
            }
        }

        // ---- advance pipeline ----
        if (kt < qt) {
            __syncthreads();
            if (kt + 2 <= qt) { prefetch(kt + 2); cp_wait<1>(); } else { cp_wait<0>(); }
            __syncthreads();
        }
    }

    // ---- epilogue: normalize, write fp16 into g_abf ----
    float inv0 = 1.0f / l0, inv1 = 1.0f / l1;
    int mg0 = b * SEQ + q0 + qrow_loc;
    int mg1 = mg0 + 8;
#pragma unroll
    for (int j = 0; j < 8; j++) {
        int col = hh * HDIM + j*8 + (lid & 3) * 2;
        __half2 hp0 = __floats2half2_rn(oacc[j][0] * inv0, oacc[j][1] * inv0);
        __half2 hp1 = __floats2half2_rn(oacc[j][2] * inv1, oacc[j][3] * inv1);
        *(__half2*)(g_abf + (size_t)mg0 * KD + col) = hp0;
        *(__half2*)(g_abf + (size_t)mg1 * KD + col) = hp1;
    }
}

// ===========================================================================
extern "C" void kernel_launch(void* const* d_in, const int* in_sizes, int n_in,
                              void* d_out, int out_size) {
    const float* x      = (const float*)d_in[0];
    const float* norm_w = (const float*)d_in[1];
    const float* w_qkv  = (const float*)d_in[2];
    const float* w_out  = (const float*)d_in[3];
    float* out = (float*)d_out;

    __half *p_abf, *p_bbf, *p_bbf2;
    cudaGetSymbolAddress((void**)&p_abf,  g_abf);
    cudaGetSymbolAddress((void**)&p_bbf,  g_bbf);
    cudaGetSymbolAddress((void**)&p_bbf2, g_bbf2);

    cudaFuncSetAttribute(attn_mma_kernel,
                         cudaFuncAttributeMaxDynamicSharedMemorySize, ATT_SMEM);

    cudaLaunchAttribute pdl[1];
    pdl[0].id = cudaLaunchAttributeProgrammaticStreamSerialization;
    pdl[0].val.programmaticStreamSerializationAllowed = 1;

    // 1. merged RMSNorm + weight convert
    prep_kernel<<<MROWS + ((EDIM+DMODEL)*DMODEL)/(256*4), 256>>>(x, norm_w, w_qkv, w_out);

    // 2. QKV projection
    {
        cudaLaunchConfig_t cfg = {};
        cfg.gridDim = dim3(EDIM/128, MROWS/128);
        cfg.blockDim = dim3(256);
        cfg.attrs = pdl; cfg.numAttrs = 1;
        cudaLaunchKernelEx(&cfg, gemm_mma_kernel<true>,
                           (const __half*)p_abf, (const __half*)p_bbf,
                           (const float*)nullptr, (float*)nullptr, (int)EDIM);
    }

    // 3. RoPE
    {
        cudaLaunchConfig_t cfg = {};
        cfg.gridDim = dim3((BH * 2 * SEQ * 16) / 256);
        cfg.blockDim = dim3(256);
        cfg.attrs = pdl; cfg.numAttrs = 1;
        cudaLaunchKernelEx(&cfg, rope_kernel);
    }

    // 4. attention (swizzled smem, 5 CTA/SM)
    {
        cudaLaunchConfig_t cfg = {};
        cfg.gridDim = dim3(SEQ/64, NHEADS, BATCH);
        cfg.blockDim = dim3(128);
        cfg.dynamicSmemBytes = ATT_SMEM;
        cfg.attrs = pdl; cfg.numAttrs = 1;
        cudaLaunchKernelEx(&cfg, attn_mma_kernel);
    }

    // 5. Output projection + residual
    {
        cudaLaunchConfig_t cfg = {};
        cfg.gridDim = dim3(DMODEL/128, MROWS/128);
        cfg.blockDim = dim3(256);
        cfg.attrs = pdl; cfg.numAttrs = 1;
        cudaLaunchKernelEx(&cfg, gemm_mma_kernel<false>,
                           (const __half*)p_abf, (const __half*)p_bbf2,
                           (const float*)x, (float*)out, (int)DMODEL);
    }
}

// round 15
// speedup vs baseline: 1.0751x; 1.0273x over previous
#include <cuda_runtime.h>
#include <cuda_fp16.h>
#include <math.h>
#include <stdint.h>

#define BATCH   2
#define SEQ     2048
#define DMODEL  1024
#define NHEADS  16
#define HDIM    64
#define MROWS   (BATCH*SEQ)        // 4096
#define EDIM    (3*DMODEL)         // 3072
#define KD      DMODEL             // GEMM K = 1024
#define NK      (KD/32)            // 32 k-chunks of 32
#define BH      (BATCH*NHEADS)     // 32

// Scratch (device globals; no runtime allocation allowed)
__device__ __align__(128) __half g_abf[MROWS*KD];      // fp16 activations (h, then attn-out)
__device__ __align__(128) __half g_bbf[EDIM*KD];       // fp16 w_qkv
__device__ __align__(128) __half g_bbf2[DMODEL*KD];    // fp16 w_out
// head-major fp16 q/k/v: [sec: q, k, v][bh][t][d]
__device__ __align__(128) __half g_split[(size_t)3*BH*SEQ*HDIM];
#define SEC_ELEMS ((size_t)BH*SEQ*HDIM)

// ===========================================================================
// helpers
// ===========================================================================
__device__ __forceinline__ void pdl_wait() {
    asm volatile("griddepcontrol.wait;" ::: "memory");
}
__device__ __forceinline__ uint32_t smem_u32(const void* p) {
    uint32_t a;
    asm("{ .reg .u64 t; cvta.to.shared.u64 t, %1; cvt.u32.u64 %0, t; }" : "=r"(a) : "l"(p));
    return a;
}
__device__ __forceinline__ void cp16(uint32_t smem, const void* g) {
    asm volatile("cp.async.cg.shared.global [%0], [%1], 16;" :: "r"(smem), "l"(g) : "memory");
}
__device__ __forceinline__ void cp_commit() {
    asm volatile("cp.async.commit_group;" ::: "memory");
}
template<int N> __device__ __forceinline__ void cp_wait() {
    asm volatile("cp.async.wait_group %0;" :: "n"(N) : "memory");
}
__device__ __forceinline__ void ldsm4(uint32_t& r0, uint32_t& r1, uint32_t& r2, uint32_t& r3,
                                      uint32_t addr) {
    asm volatile("ldmatrix.sync.aligned.m8n8.x4.shared.b16 {%0,%1,%2,%3}, [%4];"
                 : "=r"(r0), "=r"(r1), "=r"(r2), "=r"(r3) : "r"(addr));
}
__device__ __forceinline__ void ldsm4t(uint32_t& r0, uint32_t& r1, uint32_t& r2, uint32_t& r3,
                                       uint32_t addr) {
    asm volatile("ldmatrix.sync.aligned.m8n8.x4.trans.shared.b16 {%0,%1,%2,%3}, [%4];"
                 : "=r"(r0), "=r"(r1), "=r"(r2), "=r"(r3) : "r"(addr));
}
__device__ __forceinline__ void mma16816(float* d, const uint32_t* a, const uint32_t* b) {
    asm volatile("mma.sync.aligned.m16n8k16.row.col.f32.f16.f16.f32 "
                 "{%0,%1,%2,%3}, {%4,%5,%6,%7}, {%8,%9}, {%0,%1,%2,%3};"
                 : "+f"(d[0]), "+f"(d[1]), "+f"(d[2]), "+f"(d[3])
                 : "r"(a[0]), "r"(a[1]), "r"(a[2]), "r"(a[3]), "r"(b[0]), "r"(b[1]));
}
__device__ __forceinline__ uint32_t pack_f16(float a, float b) {
    __half2 t = __floats2half2_rn(a, b);
    return *(uint32_t*)&t;
}
// SW128 swizzle on a byte offset within a 64x128B tile (16B-aligned preserved)
__device__ __forceinline__ uint32_t swz(uint32_t off) {
    return off ^ ((off >> 3) & 0x70);
}

// ===========================================================================
// K1: merged RMSNorm + weight conversion (independent halves of the grid).
// ===========================================================================
__global__ void prep_kernel(const float* __restrict__ x, const float* __restrict__ w,
                            const float* __restrict__ w_qkv, const float* __restrict__ w_out) {
    int tid = threadIdx.x;
    if (blockIdx.x < MROWS) {
        int row = blockIdx.x;
        float4 v = *(const float4*)(x + (size_t)row * DMODEL + tid * 4);
        float ss = v.x*v.x + v.y*v.y + v.z*v.z + v.w*v.w;
#pragma unroll
        for (int off = 16; off > 0; off >>= 1)
            ss += __shfl_xor_sync(0xffffffffu, ss, off);
        __shared__ float red[8];
        if ((tid & 31) == 0) red[tid >> 5] = ss;
        __syncthreads();
        float tot = red[0] + red[1] + red[2] + red[3]
                  + red[4] + red[5] + red[6] + red[7];
        float inv = rsqrtf(tot * (1.0f / DMODEL) + 1e-6f);
        float4 wv = *(const float4*)(w + tid * 4);
        __half2 h0 = __floats2half2_rn(v.x * inv * wv.x, v.y * inv * wv.y);
        __half2 h1 = __floats2half2_rn(v.z * inv * wv.z, v.w * inv * wv.w);
        uint2 pack = make_uint2(*(uint32_t*)&h0, *(uint32_t*)&h1);
        *(uint2*)(g_abf + (size_t)row * KD + tid * 4) = pack;
    } else {
        int idx = (blockIdx.x - MROWS) * 256 + tid;
        int e4 = idx * 4;
        float4 v;
        __half* dst;
        if (e4 < EDIM*DMODEL) {
            v = *(const float4*)(w_qkv + e4);
            dst = g_bbf + e4;
        } else {
            int j = e4 - EDIM*DMODEL;
            v = *(const float4*)(w_out + j);
            dst = g_bbf2 + j;
        }
        __half2 h0 = __floats2half2_rn(v.x, v.y);
        __half2 h1 = __floats2half2_rn(v.z, v.w);
        uint2 pack = make_uint2(*(uint32_t*)&h0, *(uint32_t*)&h1);
        *(uint2*)dst = pack;
    }
}

// ===========================================================================
// HMMA GEMM (fp16, K=1024). QKV=true: epilogue writes fp16 head-major into
// g_split. QKV=false: float C + residual.
// ===========================================================================
template<bool QKV>
__global__ __launch_bounds__(256) void gemm_mma_kernel(
    const __half* __restrict__ A, const __half* __restrict__ Bw,
    const float* __restrict__ Rsd, float* __restrict__ C, int N)
{
    __shared__ __align__(128) __half sA[2][128*40];
    __shared__ __align__(128) __half sB[2][128*40];

    pdl_wait();

    int tid = threadIdx.x, lid = tid & 31, wid = tid >> 5;
    int wm = (wid & 1) * 64;
    int wn = (wid >> 1) * 32;
    int m0 = blockIdx.y * 128, n0 = blockIdx.x * 128;

    int ldrow = tid >> 1;
    int ldcol = (tid & 1) * 32;       // bytes
    const char* gA = (const char*)(A  + (size_t)(m0 + ldrow) * KD) + ldcol;
    const char* gB = (const char*)(Bw + (size_t)(n0 + ldrow) * KD) + ldcol;

    auto prefetch = [&](int c) {
        int s = c & 1;
        uint32_t da = smem_u32(&sA[s][ldrow * 40]) + (uint32_t)ldcol;
        uint32_t db = smem_u32(&sB[s][ldrow * 40]) + (uint32_t)ldcol;
        const char* a = gA + (size_t)c * 64;
        const char* b = gB + (size_t)c * 64;
        cp16(da, a);      cp16(da + 16, a + 16);
        cp16(db, b);      cp16(db + 16, b + 16);
        cp_commit();
    };

    float acc[4][4][4] = {};

    prefetch(0); prefetch(1);

    int g  = lid >> 3, r8 = lid & 7;
    int a_m = wm + (g & 1) * 8 + r8;
    int a_k = (g >> 1) * 8;
    int b_n = wn + (g >> 1) * 8 + r8;
    int b_k = (g & 1) * 8;

    for (int kt = 0; kt < NK; kt++) {
        int s = kt & 1;
        if (kt + 1 < NK) cp_wait<1>(); else cp_wait<0>();
        __syncthreads();

        uint32_t baseA = smem_u32(&sA[s][0]);
        uint32_t baseB = smem_u32(&sB[s][0]);
#pragma unroll
        for (int ks = 0; ks < 2; ks++) {
            uint32_t a[4][4], b[4][2];
#pragma unroll
            for (int mt = 0; mt < 4; mt++) {
                uint32_t addr = baseA + (uint32_t)(a_m + mt*16) * 80u
                                      + (uint32_t)(a_k + ks*16) * 2u;
                ldsm4(a[mt][0], a[mt][1], a[mt][2], a[mt][3], addr);
            }
#pragma unroll
            for (int nt = 0; nt < 2; nt++) {
                uint32_t r0, r1, r2, r3;
                uint32_t addr = baseB + (uint32_t)(b_n + nt*16) * 80u
                                      + (uint32_t)(b_k + ks*16) * 2u;
                ldsm4(r0, r1, r2, r3, addr);
                b[nt*2][0] = r0;   b[nt*2][1] = r1;
                b[nt*2+1][0] = r2; b[nt*2+1][1] = r3;
            }
#pragma unroll
            for (int mt = 0; mt < 4; mt++)
#pragma unroll
                for (int nn = 0; nn < 4; nn++)
                    mma16816(acc[mt][nn], a[mt], b[nn]);
        }
        __syncthreads();
        if (kt + 2 < NK) prefetch(kt + 2);
    }

    int row = lid >> 2, col = (lid & 3) * 2;
#pragma unroll
    for (int mt = 0; mt < 4; mt++) {
#pragma unroll
        for (int nn = 0; nn < 4; nn++) {
            int m = m0 + wm + mt*16 + row;
            int n = n0 + wn + nn*8 + col;
            if (QKV) {
                int sc = n >> 10, h = (n >> 6) & 15, d = n & 63;
                int t = m & (SEQ - 1), bb = m >> 11;
                size_t base = (size_t)sc * SEC_ELEMS
                            + ((size_t)(bb * NHEADS + h) * SEQ + t) * HDIM + d;
                __half2 v0 = __floats2half2_rn(acc[mt][nn][0], acc[mt][nn][1]);
                __half2 v1 = __floats2half2_rn(acc[mt][nn][2], acc[mt][nn][3]);
                *(__half2*)(g_split + base)            = v0;
                *(__half2*)(g_split + base + 8*HDIM)   = v1;
            } else {
                float2 v0 = make_float2(acc[mt][nn][0], acc[mt][nn][1]);
                float2 v1 = make_float2(acc[mt][nn][2], acc[mt][nn][3]);
                float2 q0 = *(const float2*)(Rsd + (size_t)m * N + n);
                float2 q1 = *(const float2*)(Rsd + (size_t)(m+8) * N + n);
                v0.x += q0.x; v0.y += q0.y;
                v1.x += q1.x; v1.y += q1.y;
                *(float2*)(C + (size_t)m * N + n)     = v0;
                *(float2*)(C + (size_t)(m+8) * N + n) = v1;
            }
        }
    }
}

// ===========================================================================
// K3: in-place fp16 RoPE on Q,K sections of g_split.
// ===========================================================================
__global__ void rope_kernel() {
    pdl_wait();
    int idx = blockIdx.x * 256 + threadIdx.x;   // BH*2*SEQ*16
    int k  = idx & 15;
    int t  = (idx >> 4) & (SEQ - 1);
    int sc = (idx >> 15) & 1;                   // 0 = q, 1 = k
    int bh = idx >> 16;
    __half* p = g_split + (size_t)sc * SEC_ELEMS + ((size_t)bh * SEQ + t) * HDIM + 2*k;
    float2 a = __half22float2(*(__half2*)(p));
    float2 b = __half22float2(*(__half2*)(p + 32));
    const float NEG_L2_10K_32 = -0.41524101186092029f;   // -log2(10000)/32
    float if0 = exp2f((float)(2*k)   * NEG_L2_10K_32);
    float if1 = exp2f((float)(2*k+1) * NEG_L2_10K_32);
    float s0, c0, s1, c1;
    __sincosf((float)t * if0, &s0, &c0);
    __sincosf((float)t * if1, &s1, &c1);
    float y0 = a.x*c0 - b.x*s0, y1 = a.y*c1 - b.y*s1;
    float z0 = b.x*c0 + a.x*s0, z1 = b.y*c1 + a.y*s1;
    if (sc == 0) {
        const float QS = 0.125f * 1.4426950408889634f;   // 1/sqrt(64) * log2(e)
        y0 *= QS; y1 *= QS; z0 *= QS; z1 *= QS;
    }
    *(__half2*)(p)      = __floats2half2_rn(y0, y1);
    *(__half2*)(p + 32) = __floats2half2_rn(z0, z1);
}

// ===========================================================================
// K4: HMMA causal flash attention, SW128-swizzled stride-64 smem tiles
// (8KB each; Q + 2x(K,V) = 40960 B -> 5 CTAs/SM). Single barrier per tile:
// depth-1 double buffer (prefetch kt+1 right after the top-of-iter barrier,
// which already proves all warps finished reading that stage in iter kt-1).
// Heavy-first, exp2 softmax, no Q hoist, inline P packing.
// ===========================================================================
#define TILE_B 8192                      // one 64x64 fp16 tile, swizzled
#define ATT_SMEM (5 * TILE_B)            // 40960 bytes

__global__ __launch_bounds__(128, 5) void attn_mma_kernel() {
    extern __shared__ __half sh[];
    uint32_t bQ = smem_u32(sh);          // Q tile at offset 0
    // KV stage s (0..1): K at bQ + (1 + s*2)*TILE_B, V at +TILE_B more

    pdl_wait();

    int qt = (gridDim.x - 1) - blockIdx.x;      // heavy CTAs first
    int hh = blockIdx.y, b = blockIdx.z;
    int bh = b * NHEADS + hh;
    int tid = threadIdx.x;
    int lid = tid & 31, wid = tid >> 5;
    int q0 = qt * 64;

    const __half* gq = g_split + 0*SEC_ELEMS + (size_t)bh * SEQ * HDIM;
    const __half* gk = g_split + 1*SEC_ELEMS + (size_t)bh * SEQ * HDIM;
    const __half* gv = g_split + 2*SEC_ELEMS + (size_t)bh * SEQ * HDIM;

    int ldrow = tid >> 1;          // 0..63
    int ldh   = (tid & 1) * 32;    // halfs offset within row (0 or 32 -> 64B)

    // Q load (joins group of prefetch(0)); swizzled stores
    {
        const __half* s0 = gq + (size_t)(q0 + ldrow) * HDIM + ldh;
#pragma unroll
        for (int i = 0; i < 4; i++) {
            uint32_t off = (uint32_t)ldrow * 128u + (uint32_t)ldh * 2u + i * 16u;
            cp16(bQ + swz(off), s0 + i*8);
        }
    }

    auto prefetch = [&](int kt) {
        int s = kt & 1;
        uint32_t baseK = bQ + (1 + s*2) * TILE_B;
        size_t gr = (size_t)(kt * 64 + ldrow) * HDIM + ldh;
        const __half* srcs[2] = { gk + gr, gv + gr };
#pragma unroll
        for (int a = 0; a < 2; a++) {
            uint32_t base = baseK + a * TILE_B;
#pragma unroll
            for (int i = 0; i < 4; i++) {
                uint32_t off = (uint32_t)ldrow * 128u + (uint32_t)ldh * 2u + i * 16u;
                cp16(base + swz(off), srcs[a] + i*8);
            }
        }
        cp_commit();
    };
    prefetch(0);                      // group 0 = Q + tile 0
    cp_wait<0>();
    __syncthreads();                  // Q + tile 0 visible

    int g  = lid >> 3, r8 = lid & 7;
    int a_row = wid * 16 + (g & 1) * 8 + r8;   // Q smem row
    int a_kb  = ((g >> 1) * 8) * 2;            // byte offset within row (+kc*32)
    int b_row = (g >> 1) * 8 + r8;             // K smem row within 16-pair (+p*16)
    int b_kb  = ((g & 1) * 8) * 2;
    int v_row = lid & 15;                      // + kc*16
    int v_cb  = ((lid >> 4) * 8) * 2;          // byte offset within row (+p*32)
    int qrow_loc = wid * 16 + (lid >> 2);      // local q row for c0/c1

    float m0 = -1e30f, m1 = -1e30f, l0 = 0.f, l1 = 0.f;
    float oacc[8][4] = {};

    for (int kt = 0; kt <= qt; kt++) {
        // depth-1 prefetch of next tile: safe — everyone passed the barrier,
        // so all reads of stage (kt+1)&1 (done in iter kt-1) are complete.
        if (kt < qt) prefetch(kt + 1);

        uint32_t bKh = bQ + (1 + (kt & 1)*2) * TILE_B;
        uint32_t bVh = bKh + TILE_B;

        // ---- S = Q K^T (swizzled ldsm addresses) ----
        float sacc[8][4] = {};
#pragma unroll
        for (int kc = 0; kc < 4; kc++) {
            uint32_t ah[4];
            {
                uint32_t off = (uint32_t)a_row * 128u + (uint32_t)(kc*32 + a_kb);
                ldsm4(ah[0], ah[1], ah[2], ah[3], bQ + swz(off));
            }
            uint32_t bhf[8][2];
#pragma unroll
            for (int p = 0; p < 4; p++) {
                uint32_t off = (uint32_t)(p*16 + b_row) * 128u + (uint32_t)(kc*32 + b_kb);
                uint32_t r0, r1, r2, r3;
                ldsm4(r0, r1, r2, r3, bKh + swz(off));
                bhf[2*p][0] = r0; bhf[2*p][1] = r1;
                bhf[2*p+1][0] = r2; bhf[2*p+1][1] = r3;
            }
#pragma unroll
            for (int j = 0; j < 8; j++)
                mma16816(sacc[j], ah, bhf[j]);
        }

        // ---- causal mask on diagonal tile ----
        if (kt == qt) {
#pragma unroll
            for (int j = 0; j < 8; j++) {
                int col = j*8 + (lid & 3) * 2;
                if (col     > qrow_loc)     sacc[j][0] = -1e30f;
                if (col + 1 > qrow_loc)     sacc[j][1] = -1e30f;
                if (col     > qrow_loc + 8) sacc[j][2] = -1e30f;
                if (col + 1 > qrow_loc + 8) sacc[j][3] = -1e30f;
            }
        }

        // ---- online softmax (exp2 domain), rows qrow_loc and +8 ----
        float mx0 = -1e30f, mx1 = -1e30f;
#pragma unroll
        for (int j = 0; j < 8; j++) {
            mx0 = fmaxf(mx0, fmaxf(sacc[j][0], sacc[j][1]));
            mx1 = fmaxf(mx1, fmaxf(sacc[j][2], sacc[j][3]));
        }
        mx0 = fmaxf(mx0, __shfl_xor_sync(0xffffffffu, mx0, 1));
        mx0 = fmaxf(mx0, __shfl_xor_sync(0xffffffffu, mx0, 2));
        mx1 = fmaxf(mx1, __shfl_xor_sync(0xffffffffu, mx1, 1));
        mx1 = fmaxf(mx1, __shfl_xor_sync(0xffffffffu, mx1, 2));
        float mn0 = fmaxf(m0, mx0), mn1 = fmaxf(m1, mx1);
        float al0 = exp2f(m0 - mn0), al1 = exp2f(m1 - mn1);
        float s0 = 0.f, s1 = 0.f;
#pragma unroll
        for (int j = 0; j < 8; j++) {
            sacc[j][0] = exp2f(sacc[j][0] - mn0);
            sacc[j][1] = exp2f(sacc[j][1] - mn0);
            sacc[j][2] = exp2f(sacc[j][2] - mn1);
            sacc[j][3] = exp2f(sacc[j][3] - mn1);
            s0 += sacc[j][0] + sacc[j][1];
            s1 += sacc[j][2] + sacc[j][3];
        }
        s0 += __shfl_xor_sync(0xffffffffu, s0, 1);
        s0 += __shfl_xor_sync(0xffffffffu, s0, 2);
        s1 += __shfl_xor_sync(0xffffffffu, s1, 1);
        s1 += __shfl_xor_sync(0xffffffffu, s1, 2);
        l0 = l0 * al0 + s0;  l1 = l1 * al1 + s1;
        m0 = mn0;  m1 = mn1;
#pragma unroll
        for (int j = 0; j < 8; j++) {
            oacc[j][0] *= al0; oacc[j][1] *= al0;
            oacc[j][2] *= al1; oacc[j][3] *= al1;
        }

        // ---- O += P V: P packed inline per kc; V swizzled ldsm4t ----
#pragma unroll
        for (int kc = 0; kc < 4; kc++) {
            uint32_t aH[4];
            aH[0] = pack_f16(sacc[2*kc][0],   sacc[2*kc][1]);
            aH[1] = pack_f16(sacc[2*kc][2],   sacc[2*kc][3]);
            aH[2] = pack_f16(sacc[2*kc+1][0], sacc[2*kc+1][1]);
            aH[3] = pack_f16(sacc[2*kc+1][2], sacc[2*kc+1][3]);
#pragma unroll
            for (int p = 0; p < 4; p++) {
                uint32_t off = (uint32_t)(kc*16 + v_row) * 128u + (uint32_t)(p*32 + v_cb);
                uint32_t h0, h1, h2, h3;
                ldsm4t(h0, h1, h2, h3, bVh + swz(off));
                uint32_t bv0[2] = { h0, h1 }, bv1[2] = { h2, h3 };
                mma16816(oacc[2*p],   aH, bv0);
                mma16816(oacc[2*p+1], aH, bv1);
            }
        }

        // ---- single end-of-iter barrier: next tile visible + reads drained ----
        if (kt < qt) {
            cp_wait<0>();
            __syncthreads();
        }
    }

    // ---- epilogue: normalize, write fp16 into g_abf ----
    float inv0 = 1.0f / l0, inv1 = 1.0f / l1;
    int mg0 = b * SEQ + q0 + qrow_loc;
    int mg1 = mg0 + 8;
#pragma unroll
    for (int j = 0; j < 8; j++) {
        int col = hh * HDIM + j*8 + (lid & 3) * 2;
        __half2 hp0 = __floats2half2_rn(oacc[j][0] * inv0, oacc[j][1] * inv0);
        __half2 hp1 = __floats2half2_rn(oacc[j][2] * inv1, oacc[j][3] * inv1);
        *(__half2*)(g_abf + (size_t)mg0 * KD + col) = hp0;
        *(__half2*)(g_abf + (size_t)mg1 * KD + col) = hp1;
    }
}

// ===========================================================================
extern "C" void kernel_launch(void* const* d_in, const int* in_sizes, int n_in,
                              void* d_out, int out_size) {
    const float* x      = (const float*)d_in[0];
    const float* norm_w = (const float*)d_in[1];
    const float* w_qkv  = (const float*)d_in[2];
    const float* w_out  = (const float*)d_in[3];
    float* out = (float*)d_out;

    __half *p_abf, *p_bbf, *p_bbf2;
    cudaGetSymbolAddress((void**)&p_abf,  g_abf);
    cudaGetSymbolAddress((void**)&p_bbf,  g_bbf);
    cudaGetSymbolAddress((void**)&p_bbf2, g_bbf2);

    cudaFuncSetAttribute(attn_mma_kernel,
                         cudaFuncAttributeMaxDynamicSharedMemorySize, ATT_SMEM);

    cudaLaunchAttribute pdl[1];
    pdl[0].id = cudaLaunchAttributeProgrammaticStreamSerialization;
    pdl[0].val.programmaticStreamSerializationAllowed = 1;

    // 1. merged RMSNorm + weight convert
    prep_kernel<<<MROWS + ((EDIM+DMODEL)*DMODEL)/(256*4), 256>>>(x, norm_w, w_qkv, w_out);

    // 2. QKV projection
    {
        cudaLaunchConfig_t cfg = {};
        cfg.gridDim = dim3(EDIM/128, MROWS/128);
        cfg.blockDim = dim3(256);
        cfg.attrs = pdl; cfg.numAttrs = 1;
        cudaLaunchKernelEx(&cfg, gemm_mma_kernel<true>,
                           (const __half*)p_abf, (const __half*)p_bbf,
                           (const float*)nullptr, (float*)nullptr, (int)EDIM);
    }

    // 3. RoPE
    {
        cudaLaunchConfig_t cfg = {};
        cfg.gridDim = dim3((BH * 2 * SEQ * 16) / 256);
        cfg.blockDim = dim3(256);
        cfg.attrs = pdl; cfg.numAttrs = 1;
        cudaLaunchKernelEx(&cfg, rope_kernel);
    }

    // 4. attention (swizzled smem, 5 CTA/SM, single barrier per tile)
    {
        cudaLaunchConfig_t cfg = {};
        cfg.gridDim = dim3(SEQ/64, NHEADS, BATCH);
        cfg.blockDim = dim3(128);
        cfg.dynamicSmemBytes = ATT_SMEM;
        cfg.attrs = pdl; cfg.numAttrs = 1;
        cudaLaunchKernelEx(&cfg, attn_mma_kernel);
    }

    // 5. Output projection + residual
    {
        cudaLaunchConfig_t cfg = {};
        cfg.gridDim = dim3(DMODEL/128, MROWS/128);
        cfg.blockDim = dim3(256);
        cfg.attrs = pdl; cfg.numAttrs = 1;
        cudaLaunchKernelEx(&cfg, gemm_mma_kernel<false>,
                           (const __half*)p_abf, (const __half*)p_bbf2,
                           (const float*)x, (float*)out, (int)DMODEL);
    }
}

// round 16
// speedup vs baseline: 1.0775x; 1.0022x over previous
#include <cuda_runtime.h>
#include <cuda_fp16.h>
#include <math.h>
#include <stdint.h>

#define BATCH   2
#define SEQ     2048
#define DMODEL  1024
#define NHEADS  16
#define HDIM    64
#define MROWS   (BATCH*SEQ)        // 4096
#define EDIM    (3*DMODEL)         // 3072
#define KD      DMODEL             // GEMM K = 1024
#define NK      (KD/32)            // 32 k-chunks of 32
#define BH      (BATCH*NHEADS)     // 32

// Scratch (device globals; no runtime allocation allowed)
__device__ __align__(128) __half g_abf[MROWS*KD];      // fp16 activations (h, then attn-out)
__device__ __align__(128) __half g_bbf[EDIM*KD];       // fp16 w_qkv
__device__ __align__(128) __half g_bbf2[DMODEL*KD];    // fp16 w_out
// head-major fp16 q/k/v: [sec: q, k, v][bh][t][d]
__device__ __align__(128) __half g_split[(size_t)3*BH*SEQ*HDIM];
#define SEC_ELEMS ((size_t)BH*SEQ*HDIM)

// ===========================================================================
// helpers
// ===========================================================================
__device__ __forceinline__ void pdl_wait() {
    asm volatile("griddepcontrol.wait;" ::: "memory");
}
__device__ __forceinline__ uint32_t smem_u32(const void* p) {
    uint32_t a;
    asm("{ .reg .u64 t; cvta.to.shared.u64 t, %1; cvt.u32.u64 %0, t; }" : "=r"(a) : "l"(p));
    return a;
}
__device__ __forceinline__ void cp16(uint32_t smem, const void* g) {
    asm volatile("cp.async.cg.shared.global [%0], [%1], 16;" :: "r"(smem), "l"(g) : "memory");
}
__device__ __forceinline__ void cp_commit() {
    asm volatile("cp.async.commit_group;" ::: "memory");
}
template<int N> __device__ __forceinline__ void cp_wait() {
    asm volatile("cp.async.wait_group %0;" :: "n"(N) : "memory");
}
__device__ __forceinline__ void ldsm4(uint32_t& r0, uint32_t& r1, uint32_t& r2, uint32_t& r3,
                                      uint32_t addr) {
    asm volatile("ldmatrix.sync.aligned.m8n8.x4.shared.b16 {%0,%1,%2,%3}, [%4];"
                 : "=r"(r0), "=r"(r1), "=r"(r2), "=r"(r3) : "r"(addr));
}
__device__ __forceinline__ void ldsm4t(uint32_t& r0, uint32_t& r1, uint32_t& r2, uint32_t& r3,
                                       uint32_t addr) {
    asm volatile("ldmatrix.sync.aligned.m8n8.x4.trans.shared.b16 {%0,%1,%2,%3}, [%4];"
                 : "=r"(r0), "=r"(r1), "=r"(r2), "=r"(r3) : "r"(addr));
}
__device__ __forceinline__ void mma16816(float* d, const uint32_t* a, const uint32_t* b) {
    asm volatile("mma.sync.aligned.m16n8k16.row.col.f32.f16.f16.f32 "
                 "{%0,%1,%2,%3}, {%4,%5,%6,%7}, {%8,%9}, {%0,%1,%2,%3};"
                 : "+f"(d[0]), "+f"(d[1]), "+f"(d[2]), "+f"(d[3])
                 : "r"(a[0]), "r"(a[1]), "r"(a[2]), "r"(a[3]), "r"(b[0]), "r"(b[1]));
}
// packed fp16x2 exp2 (single MUFU op for two values)
__device__ __forceinline__ uint32_t h2exp2(uint32_t x) {
    uint32_t r;
    asm volatile("ex2.approx.f16x2 %0, %1;" : "=r"(r) : "r"(x));
    return r;
}
__device__ __forceinline__ uint32_t h2pack(float a, float b) {
    __half2 t = __floats2half2_rn(a, b);
    return *(uint32_t*)&t;
}
__device__ __forceinline__ uint32_t h2add(uint32_t a, uint32_t b) {
    __half2 r = __hadd2(*(__half2*)&a, *(__half2*)&b);
    return *(uint32_t*)&r;
}
// SW128 swizzle on a byte offset within a 64x128B tile (16B-aligned preserved)
__device__ __forceinline__ uint32_t swz(uint32_t off) {
    return off ^ ((off >> 3) & 0x70);
}

// ===========================================================================
// K1: merged RMSNorm + weight conversion (independent halves of the grid).
// ===========================================================================
__global__ void prep_kernel(const float* __restrict__ x, const float* __restrict__ w,
                            const float* __restrict__ w_qkv, const float* __restrict__ w_out) {
    int tid = threadIdx.x;
    if (blockIdx.x < MROWS) {
        int row = blockIdx.x;
        float4 v = *(const float4*)(x + (size_t)row * DMODEL + tid * 4);
        float ss = v.x*v.x + v.y*v.y + v.z*v.z + v.w*v.w;
#pragma unroll
        for (int off = 16; off > 0; off >>= 1)
            ss += __shfl_xor_sync(0xffffffffu, ss, off);
        __shared__ float red[8];
        if ((tid & 31) == 0) red[tid >> 5] = ss;
        __syncthreads();
        float tot = red[0] + red[1] + red[2] + red[3]
                  + red[4] + red[5] + red[6] + red[7];
        float inv = rsqrtf(tot * (1.0f / DMODEL) + 1e-6f);
        float4 wv = *(const float4*)(w + tid * 4);
        __half2 h0 = __floats2half2_rn(v.x * inv * wv.x, v.y * inv * wv.y);
        __half2 h1 = __floats2half2_rn(v.z * inv * wv.z, v.w * inv * wv.w);
        uint2 pack = make_uint2(*(uint32_t*)&h0, *(uint32_t*)&h1);
        *(uint2*)(g_abf + (size_t)row * KD + tid * 4) = pack;
    } else {
        int idx = (blockIdx.x - MROWS) * 256 + tid;
        int e4 = idx * 4;
        float4 v;
        __half* dst;
        if (e4 < EDIM*DMODEL) {
            v = *(const float4*)(w_qkv + e4);
            dst = g_bbf + e4;
        } else {
            int j = e4 - EDIM*DMODEL;
            v = *(const float4*)(w_out + j);
            dst = g_bbf2 + j;
        }
        __half2 h0 = __floats2half2_rn(v.x, v.y);
        __half2 h1 = __floats2half2_rn(v.z, v.w);
        uint2 pack = make_uint2(*(uint32_t*)&h0, *(uint32_t*)&h1);
        *(uint2*)dst = pack;
    }
}

// ===========================================================================
// HMMA GEMM (fp16, K=1024). QKV=true: epilogue writes fp16 head-major into
// g_split. QKV=false: float C + residual.
// ===========================================================================
template<bool QKV>
__global__ __launch_bounds__(256) void gemm_mma_kernel(
    const __half* __restrict__ A, const __half* __restrict__ Bw,
    const float* __restrict__ Rsd, float* __restrict__ C, int N)
{
    __shared__ __align__(128) __half sA[2][128*40];
    __shared__ __align__(128) __half sB[2][128*40];

    pdl_wait();

    int tid = threadIdx.x, lid = tid & 31, wid = tid >> 5;
    int wm = (wid & 1) * 64;
    int wn = (wid >> 1) * 32;
    int m0 = blockIdx.y * 128, n0 = blockIdx.x * 128;

    int ldrow = tid >> 1;
    int ldcol = (tid & 1) * 32;       // bytes
    const char* gA = (const char*)(A  + (size_t)(m0 + ldrow) * KD) + ldcol;
    const char* gB = (const char*)(Bw + (size_t)(n0 + ldrow) * KD) + ldcol;

    auto prefetch = [&](int c) {
        int s = c & 1;
        uint32_t da = smem_u32(&sA[s][ldrow * 40]) + (uint32_t)ldcol;
        uint32_t db = smem_u32(&sB[s][ldrow * 40]) + (uint32_t)ldcol;
        const char* a = gA + (size_t)c * 64;
        const char* b = gB + (size_t)c * 64;
        cp16(da, a);      cp16(da + 16, a + 16);
        cp16(db, b);      cp16(db + 16, b + 16);
        cp_commit();
    };

    float acc[4][4][4] = {};

    prefetch(0); prefetch(1);

    int g  = lid >> 3, r8 = lid & 7;
    int a_m = wm + (g & 1) * 8 + r8;
    int a_k = (g >> 1) * 8;
    int b_n = wn + (g >> 1) * 8 + r8;
    int b_k = (g & 1) * 8;

    for (int kt = 0; kt < NK; kt++) {
        int s = kt & 1;
        if (kt + 1 < NK) cp_wait<1>(); else cp_wait<0>();
        __syncthreads();

        uint32_t baseA = smem_u32(&sA[s][0]);
        uint32_t baseB = smem_u32(&sB[s][0]);
#pragma unroll
        for (int ks = 0; ks < 2; ks++) {
            uint32_t a[4][4], b[4][2];
#pragma unroll
            for (int mt = 0; mt < 4; mt++) {
                uint32_t addr = baseA + (uint32_t)(a_m + mt*16) * 80u
                                      + (uint32_t)(a_k + ks*16) * 2u;
                ldsm4(a[mt][0], a[mt][1], a[mt][2], a[mt][3], addr);
            }
#pragma unroll
            for (int nt = 0; nt < 2; nt++) {
                uint32_t r0, r1, r2, r3;
                uint32_t addr = baseB + (uint32_t)(b_n + nt*16) * 80u
                                      + (uint32_t)(b_k + ks*16) * 2u;
                ldsm4(r0, r1, r2, r3, addr);
                b[nt*2][0] = r0;   b[nt*2][1] = r1;
                b[nt*2+1][0] = r2; b[nt*2+1][1] = r3;
            }
#pragma unroll
            for (int mt = 0; mt < 4; mt++)
#pragma unroll
                for (int nn = 0; nn < 4; nn++)
                    mma16816(acc[mt][nn], a[mt], b[nn]);
        }
        __syncthreads();
        if (kt + 2 < NK) prefetch(kt + 2);
    }

    int row = lid >> 2, col = (lid & 3) * 2;
#pragma unroll
    for (int mt = 0; mt < 4; mt++) {
#pragma unroll
        for (int nn = 0; nn < 4; nn++) {
            int m = m0 + wm + mt*16 + row;
            int n = n0 + wn + nn*8 + col;
            if (QKV) {
                int sc = n >> 10, h = (n >> 6) & 15, d = n & 63;
                int t = m & (SEQ - 1), bb = m >> 11;
                size_t base = (size_t)sc * SEC_ELEMS
                            + ((size_t)(bb * NHEADS + h) * SEQ + t) * HDIM + d;
                __half2 v0 = __floats2half2_rn(acc[mt][nn][0], acc[mt][nn][1]);
                __half2 v1 = __floats2half2_rn(acc[mt][nn][2], acc[mt][nn][3]);
                *(__half2*)(g_split + base)            = v0;
                *(__half2*)(g_split + base + 8*HDIM)   = v1;
            } else {
                float2 v0 = make_float2(acc[mt][nn][0], acc[mt][nn][1]);
                float2 v1 = make_float2(acc[mt][nn][2], acc[mt][nn][3]);
                float2 q0 = *(const float2*)(Rsd + (size_t)m * N + n);
                float2 q1 = *(const float2*)(Rsd + (size_t)(m+8) * N + n);
                v0.x += q0.x; v0.y += q0.y;
                v1.x += q1.x; v1.y += q1.y;
                *(float2*)(C + (size_t)m * N + n)     = v0;
                *(float2*)(C + (size_t)(m+8) * N + n) = v1;
            }
        }
    }
}

// ===========================================================================
// K3: in-place fp16 RoPE on Q,K sections of g_split.
// ===========================================================================
__global__ void rope_kernel() {
    pdl_wait();
    int idx = blockIdx.x * 256 + threadIdx.x;   // BH*2*SEQ*16
    int k  = idx & 15;
    int t  = (idx >> 4) & (SEQ - 1);
    int sc = (idx >> 15) & 1;                   // 0 = q, 1 = k
    int bh = idx >> 16;
    __half* p = g_split + (size_t)sc * SEC_ELEMS + ((size_t)bh * SEQ + t) * HDIM + 2*k;
    float2 a = __half22float2(*(__half2*)(p));
    float2 b = __half22float2(*(__half2*)(p + 32));
    const float NEG_L2_10K_32 = -0.41524101186092029f;   // -log2(10000)/32
    float if0 = exp2f((float)(2*k)   * NEG_L2_10K_32);
    float if1 = exp2f((float)(2*k+1) * NEG_L2_10K_32);
    float s0, c0, s1, c1;
    __sincosf((float)t * if0, &s0, &c0);
    __sincosf((float)t * if1, &s1, &c1);
    float y0 = a.x*c0 - b.x*s0, y1 = a.y*c1 - b.y*s1;
    float z0 = b.x*c0 + a.x*s0, z1 = b.y*c1 + a.y*s1;
    if (sc == 0) {
        const float QS = 0.125f * 1.4426950408889634f;   // 1/sqrt(64) * log2(e)
        y0 *= QS; y1 *= QS; z0 *= QS; z1 *= QS;
    }
    *(__half2*)(p)      = __floats2half2_rn(y0, y1);
    *(__half2*)(p + 32) = __floats2half2_rn(z0, z1);
}

// ===========================================================================
// K4: HMMA causal flash attention, SW128-swizzled 8KB tiles, 5 CTAs/SM,
// single barrier per tile, P via ex2.approx.f16x2 (half the MUFU ops),
// half2 tree row-sum. Heavy-first, exp2 softmax.
// ===========================================================================
#define TILE_B 8192                      // one 64x64 fp16 tile, swizzled
#define ATT_SMEM (5 * TILE_B)            // 40960 bytes

__global__ __launch_bounds__(128, 5) void attn_mma_kernel() {
    extern __shared__ __half sh[];
    uint32_t bQ = smem_u32(sh);          // Q tile at offset 0
    // KV stage s (0..1): K at bQ + (1 + s*2)*TILE_B, V at +TILE_B more

    pdl_wait();

    int qt = (gridDim.x - 1) - blockIdx.x;      // heavy CTAs first
    int hh = blockIdx.y, b = blockIdx.z;
    int bh = b * NHEADS + hh;
    int tid = threadIdx.x;
    int lid = tid & 31, wid = tid >> 5;
    int q0 = qt * 64;

    const __half* gq = g_split + 0*SEC_ELEMS + (size_t)bh * SEQ * HDIM;
    const __half* gk = g_split + 1*SEC_ELEMS + (size_t)bh * SEQ * HDIM;
    const __half* gv = g_split + 2*SEC_ELEMS + (size_t)bh * SEQ * HDIM;

    int ldrow = tid >> 1;          // 0..63
    int ldh   = (tid & 1) * 32;    // halfs offset within row (0 or 32 -> 64B)

    // Q load (joins group of prefetch(0)); swizzled stores
    {
        const __half* s0 = gq + (size_t)(q0 + ldrow) * HDIM + ldh;
#pragma unroll
        for (int i = 0; i < 4; i++) {
            uint32_t off = (uint32_t)ldrow * 128u + (uint32_t)ldh * 2u + i * 16u;
            cp16(bQ + swz(off), s0 + i*8);
        }
    }

    auto prefetch = [&](int kt) {
        int s = kt & 1;
        uint32_t baseK = bQ + (1 + s*2) * TILE_B;
        size_t gr = (size_t)(kt * 64 + ldrow) * HDIM + ldh;
        const __half* srcs[2] = { gk + gr, gv + gr };
#pragma unroll
        for (int a = 0; a < 2; a++) {
            uint32_t base = baseK + a * TILE_B;
#pragma unroll
            for (int i = 0; i < 4; i++) {
                uint32_t off = (uint32_t)ldrow * 128u + (uint32_t)ldh * 2u + i * 16u;
                cp16(base + swz(off), srcs[a] + i*8);
            }
        }
        cp_commit();
    };
    prefetch(0);                      // group 0 = Q + tile 0
    cp_wait<0>();
    __syncthreads();                  // Q + tile 0 visible

    int g  = lid >> 3, r8 = lid & 7;
    int a_row = wid * 16 + (g & 1) * 8 + r8;   // Q smem row
    int a_kb  = ((g >> 1) * 8) * 2;            // byte offset within row (+kc*32)
    int b_row = (g >> 1) * 8 + r8;             // K smem row within 16-pair (+p*16)
    int b_kb  = ((g & 1) * 8) * 2;
    int v_row = lid & 15;                      // + kc*16
    int v_cb  = ((lid >> 4) * 8) * 2;          // byte offset within row (+p*32)
    int qrow_loc = wid * 16 + (lid >> 2);      // local q row for c0/c1

    float m0 = -1e30f, m1 = -1e30f, l0 = 0.f, l1 = 0.f;
    float oacc[8][4] = {};

    for (int kt = 0; kt <= qt; kt++) {
        // depth-1 prefetch of next tile (safe after top-of-iter barrier)
        if (kt < qt) prefetch(kt + 1);

        uint32_t bKh = bQ + (1 + (kt & 1)*2) * TILE_B;
        uint32_t bVh = bKh + TILE_B;

        // ---- S = Q K^T (swizzled ldsm addresses) ----
        float sacc[8][4] = {};
#pragma unroll
        for (int kc = 0; kc < 4; kc++) {
            uint32_t ah[4];
            {
                uint32_t off = (uint32_t)a_row * 128u + (uint32_t)(kc*32 + a_kb);
                ldsm4(ah[0], ah[1], ah[2], ah[3], bQ + swz(off));
            }
            uint32_t bhf[8][2];
#pragma unroll
            for (int p = 0; p < 4; p++) {
                uint32_t off = (uint32_t)(p*16 + b_row) * 128u + (uint32_t)(kc*32 + b_kb);
                uint32_t r0, r1, r2, r3;
                ldsm4(r0, r1, r2, r3, bKh + swz(off));
                bhf[2*p][0] = r0; bhf[2*p][1] = r1;
                bhf[2*p+1][0] = r2; bhf[2*p+1][1] = r3;
            }
#pragma unroll
            for (int j = 0; j < 8; j++)
                mma16816(sacc[j], ah, bhf[j]);
        }

        // ---- causal mask on diagonal tile ----
        if (kt == qt) {
#pragma unroll
            for (int j = 0; j < 8; j++) {
                int col = j*8 + (lid & 3) * 2;
                if (col     > qrow_loc)     sacc[j][0] = -1e30f;
                if (col + 1 > qrow_loc)     sacc[j][1] = -1e30f;
                if (col     > qrow_loc + 8) sacc[j][2] = -1e30f;
                if (col + 1 > qrow_loc + 8) sacc[j][3] = -1e30f;
            }
        }

        // ---- online softmax (exp2 domain), rows qrow_loc and +8 ----
        float mx0 = -1e30f, mx1 = -1e30f;
#pragma unroll
        for (int j = 0; j < 8; j++) {
            mx0 = fmaxf(mx0, fmaxf(sacc[j][0], sacc[j][1]));
            mx1 = fmaxf(mx1, fmaxf(sacc[j][2], sacc[j][3]));
        }
        mx0 = fmaxf(mx0, __shfl_xor_sync(0xffffffffu, mx0, 1));
        mx0 = fmaxf(mx0, __shfl_xor_sync(0xffffffffu, mx0, 2));
        mx1 = fmaxf(mx1, __shfl_xor_sync(0xffffffffu, mx1, 1));
        mx1 = fmaxf(mx1, __shfl_xor_sync(0xffffffffu, mx1, 2));
        float mn0 = fmaxf(m0, mx0), mn1 = fmaxf(m1, mx1);
        float al0 = exp2f(m0 - mn0), al1 = exp2f(m1 - mn1);

        // P = exp2(S - m) via packed fp16x2 MUFU; outputs ARE the PV A-frags
        uint32_t p01[8], p23[8];
#pragma unroll
        for (int j = 0; j < 8; j++) {
            p01[j] = h2exp2(h2pack(sacc[j][0] - mn0, sacc[j][1] - mn0));
            p23[j] = h2exp2(h2pack(sacc[j][2] - mn1, sacc[j][3] - mn1));
        }
        // half2 pairwise-tree row sums (depth 3), then to fp32
        uint32_t t01 = h2add(h2add(h2add(p01[0], p01[1]), h2add(p01[2], p01[3])),
                             h2add(h2add(p01[4], p01[5]), h2add(p01[6], p01[7])));
        uint32_t t23 = h2add(h2add(h2add(p23[0], p23[1]), h2add(p23[2], p23[3])),
                             h2add(h2add(p23[4], p23[5]), h2add(p23[6], p23[7])));
        float2 f01 = __half22float2(*(__half2*)&t01);
        float2 f23 = __half22float2(*(__half2*)&t23);
        float s0 = f01.x + f01.y;
        float s1 = f23.x + f23.y;
        s0 += __shfl_xor_sync(0xffffffffu, s0, 1);
        s0 += __shfl_xor_sync(0xffffffffu, s0, 2);
        s1 += __shfl_xor_sync(0xffffffffu, s1, 1);
        s1 += __shfl_xor_sync(0xffffffffu, s1, 2);
        l0 = l0 * al0 + s0;  l1 = l1 * al1 + s1;
        m0 = mn0;  m1 = mn1;
#pragma unroll
        for (int j = 0; j < 8; j++) {
            oacc[j][0] *= al0; oacc[j][1] *= al0;
            oacc[j][2] *= al1; oacc[j][3] *= al1;
        }

        // ---- O += P V: A-frags straight from p01/p23; V swizzled ldsm4t ----
#pragma unroll
        for (int kc = 0; kc < 4; kc++) {
            uint32_t aH[4] = { p01[2*kc], p23[2*kc], p01[2*kc+1], p23[2*kc+1] };
#pragma unroll
            for (int p = 0; p < 4; p++) {
                uint32_t off = (uint32_t)(kc*16 + v_row) * 128u + (uint32_t)(p*32 + v_cb);
                uint32_t h0, h1, h2, h3;
                ldsm4t(h0, h1, h2, h3, bVh + swz(off));
                uint32_t bv0[2] = { h0, h1 }, bv1[2] = { h2, h3 };
                mma16816(oacc[2*p],   aH, bv0);
                mma16816(oacc[2*p+1], aH, bv1);
            }
        }

        // ---- single end-of-iter barrier: next tile visible + reads drained ----
        if (kt < qt) {
            cp_wait<0>();
            __syncthreads();
        }
    }

    // ---- epilogue: normalize, write fp16 into g_abf ----
    float inv0 = 1.0f / l0, inv1 = 1.0f / l1;
    int mg0 = b * SEQ + q0 + qrow_loc;
    int mg1 = mg0 + 8;
#pragma unroll
    for (int j = 0; j < 8; j++) {
        int col = hh * HDIM + j*8 + (lid & 3) * 2;
        __half2 hp0 = __floats2half2_rn(oacc[j][0] * inv0, oacc[j][1] * inv0);
        __half2 hp1 = __floats2half2_rn(oacc[j][2] * inv1, oacc[j][3] * inv1);
        *(__half2*)(g_abf + (size_t)mg0 * KD + col) = hp0;
        *(__half2*)(g_abf + (size_t)mg1 * KD + col) = hp1;
    }
}

// ===========================================================================
extern "C" void kernel_launch(void* const* d_in, const int* in_sizes, int n_in,
                              void* d_out, int out_size) {
    const float* x      = (const float*)d_in[0];
    const float* norm_w = (const float*)d_in[1];
    const float* w_qkv  = (const float*)d_in[2];
    const float* w_out  = (const float*)d_in[3];
    float* out = (float*)d_out;

    __half *p_abf, *p_bbf, *p_bbf2;
    cudaGetSymbolAddress((void**)&p_abf,  g_abf);
    cudaGetSymbolAddress((void**)&p_bbf,  g_bbf);
    cudaGetSymbolAddress((void**)&p_bbf2, g_bbf2);

    cudaFuncSetAttribute(attn_mma_kernel,
                         cudaFuncAttributeMaxDynamicSharedMemorySize, ATT_SMEM);

    cudaLaunchAttribute pdl[1];
    pdl[0].id = cudaLaunchAttributeProgrammaticStreamSerialization;
    pdl[0].val.programmaticStreamSerializationAllowed = 1;

    // 1. merged RMSNorm + weight convert
    prep_kernel<<<MROWS + ((EDIM+DMODEL)*DMODEL)/(256*4), 256>>>(x, norm_w, w_qkv, w_out);

    // 2. QKV projection
    {
        cudaLaunchConfig_t cfg = {};
        cfg.gridDim = dim3(EDIM/128, MROWS/128);
        cfg.blockDim = dim3(256);
        cfg.attrs = pdl; cfg.numAttrs = 1;
        cudaLaunchKernelEx(&cfg, gemm_mma_kernel<true>,
                           (const __half*)p_abf, (const __half*)p_bbf,
                           (const float*)nullptr, (float*)nullptr, (int)EDIM);
    }

    // 3. RoPE
    {
        cudaLaunchConfig_t cfg = {};
        cfg.gridDim = dim3((BH * 2 * SEQ * 16) / 256);
        cfg.blockDim = dim3(256);
        cfg.attrs = pdl; cfg.numAttrs = 1;
        cudaLaunchKernelEx(&cfg, rope_kernel);
    }

    // 4. attention (f16x2 exp softmax, 5 CTA/SM, single barrier/tile)
    {
        cudaLaunchConfig_t cfg = {};
        cfg.gridDim = dim3(SEQ/64, NHEADS, BATCH);
        cfg.blockDim = dim3(128);
        cfg.dynamicSmemBytes = ATT_SMEM;
        cfg.attrs = pdl; cfg.numAttrs = 1;
        cudaLaunchKernelEx(&cfg, attn_mma_kernel);
    }

    // 5. Output projection + residual
    {
        cudaLaunchConfig_t cfg = {};
        cfg.gridDim = dim3(DMODEL/128, MROWS/128);
        cfg.blockDim = dim3(256);
        cfg.attrs = pdl; cfg.numAttrs = 1;
        cudaLaunchKernelEx(&cfg, gemm_mma_kernel<false>,
                           (const __half*)p_abf, (const __half*)p_bbf2,
                           (const float*)x, (float*)out, (int)DMODEL);
    }
}

// round 17
// speedup vs baseline: 1.1112x; 1.0313x over previous
#include <cuda_runtime.h>
#include <cuda_fp16.h>
#include <math.h>
#include <stdint.h>

#define BATCH   2
#define SEQ     2048
#define DMODEL  1024
#define NHEADS  16
#define HDIM    64
#define MROWS   (BATCH*SEQ)        // 4096
#define EDIM    (3*DMODEL)         // 3072
#define KD      DMODEL             // GEMM K = 1024
#define NK      (KD/32)            // 32 k-chunks of 32
#define BH      (BATCH*NHEADS)     // 32
#define NQT     (SEQ/64)           // 32 q tiles per head
#define NSPLIT  16                 // qt >= NSPLIT gets 2 CTAs

// Scratch (device globals; no runtime allocation allowed)
__device__ __align__(128) __half g_abf[MROWS*KD];      // fp16 activations
__device__ __align__(128) __half g_bbf[EDIM*KD];       // fp16 w_qkv
__device__ __align__(128) __half g_bbf2[DMODEL*KD];    // fp16 w_out
__device__ __align__(128) __half g_split[(size_t)3*BH*SEQ*HDIM];
#define SEC_ELEMS ((size_t)BH*SEQ*HDIM)
// split-KV partials: [part][bh][q16][row][dim] fp32, + (m,l) per row
#define PO_STRIDE ((size_t)BH*16*64*64)                // per-part floats
__device__ float  g_po[2*PO_STRIDE];                   // 16.8 MB
__device__ float2 g_pml[(size_t)2*BH*16*64];           // (m,l)

// ===========================================================================
// helpers
// ===========================================================================
__device__ __forceinline__ void pdl_wait() {
    asm volatile("griddepcontrol.wait;" ::: "memory");
}
__device__ __forceinline__ uint32_t smem_u32(const void* p) {
    uint32_t a;
    asm("{ .reg .u64 t; cvta.to.shared.u64 t, %1; cvt.u32.u64 %0, t; }" : "=r"(a) : "l"(p));
    return a;
}
__device__ __forceinline__ void cp16(uint32_t smem, const void* g) {
    asm volatile("cp.async.cg.shared.global [%0], [%1], 16;" :: "r"(smem), "l"(g) : "memory");
}
__device__ __forceinline__ void cp_commit() {
    asm volatile("cp.async.commit_group;" ::: "memory");
}
template<int N> __device__ __forceinline__ void cp_wait() {
    asm volatile("cp.async.wait_group %0;" :: "n"(N) : "memory");
}
__device__ __forceinline__ void ldsm4(uint32_t& r0, uint32_t& r1, uint32_t& r2, uint32_t& r3,
                                      uint32_t addr) {
    asm volatile("ldmatrix.sync.aligned.m8n8.x4.shared.b16 {%0,%1,%2,%3}, [%4];"
                 : "=r"(r0), "=r"(r1), "=r"(r2), "=r"(r3) : "r"(addr));
}
__device__ __forceinline__ void ldsm4t(uint32_t& r0, uint32_t& r1, uint32_t& r2, uint32_t& r3,
                                       uint32_t addr) {
    asm volatile("ldmatrix.sync.aligned.m8n8.x4.trans.shared.b16 {%0,%1,%2,%3}, [%4];"
                 : "=r"(r0), "=r"(r1), "=r"(r2), "=r"(r3) : "r"(addr));
}
__device__ __forceinline__ void mma16816(float* d, const uint32_t* a, const uint32_t* b) {
    asm volatile("mma.sync.aligned.m16n8k16.row.col.f32.f16.f16.f32 "
                 "{%0,%1,%2,%3}, {%4,%5,%6,%7}, {%8,%9}, {%0,%1,%2,%3};"
                 : "+f"(d[0]), "+f"(d[1]), "+f"(d[2]), "+f"(d[3])
                 : "r"(a[0]), "r"(a[1]), "r"(a[2]), "r"(a[3]), "r"(b[0]), "r"(b[1]));
}
__device__ __forceinline__ uint32_t h2exp2(uint32_t x) {
    uint32_t r;
    asm volatile("ex2.approx.f16x2 %0, %1;" : "=r"(r) : "r"(x));
    return r;
}
__device__ __forceinline__ uint32_t h2pack(float a, float b) {
    __half2 t = __floats2half2_rn(a, b);
    return *(uint32_t*)&t;
}
__device__ __forceinline__ uint32_t h2add(uint32_t a, uint32_t b) {
    __half2 r = __hadd2(*(__half2*)&a, *(__half2*)&b);
    return *(uint32_t*)&r;
}
__device__ __forceinline__ uint32_t swz(uint32_t off) {
    return off ^ ((off >> 3) & 0x70);
}

// ===========================================================================
// K1: merged RMSNorm + weight conversion.
// ===========================================================================
__global__ void prep_kernel(const float* __restrict__ x, const float* __restrict__ w,
                            const float* __restrict__ w_qkv, const float* __restrict__ w_out) {
    int tid = threadIdx.x;
    if (blockIdx.x < MROWS) {
        int row = blockIdx.x;
        float4 v = *(const float4*)(x + (size_t)row * DMODEL + tid * 4);
        float ss = v.x*v.x + v.y*v.y + v.z*v.z + v.w*v.w;
#pragma unroll
        for (int off = 16; off > 0; off >>= 1)
            ss += __shfl_xor_sync(0xffffffffu, ss, off);
        __shared__ float red[8];
        if ((tid & 31) == 0) red[tid >> 5] = ss;
        __syncthreads();
        float tot = red[0] + red[1] + red[2] + red[3]
                  + red[4] + red[5] + red[6] + red[7];
        float inv = rsqrtf(tot * (1.0f / DMODEL) + 1e-6f);
        float4 wv = *(const float4*)(w + tid * 4);
        __half2 h0 = __floats2half2_rn(v.x * inv * wv.x, v.y * inv * wv.y);
        __half2 h1 = __floats2half2_rn(v.z * inv * wv.z, v.w * inv * wv.w);
        uint2 pack = make_uint2(*(uint32_t*)&h0, *(uint32_t*)&h1);
        *(uint2*)(g_abf + (size_t)row * KD + tid * 4) = pack;
    } else {
        int idx = (blockIdx.x - MROWS) * 256 + tid;
        int e4 = idx * 4;
        float4 v;
        __half* dst;
        if (e4 < EDIM*DMODEL) {
            v = *(const float4*)(w_qkv + e4);
            dst = g_bbf + e4;
        } else {
            int j = e4 - EDIM*DMODEL;
            v = *(const float4*)(w_out + j);
            dst = g_bbf2 + j;
        }
        __half2 h0 = __floats2half2_rn(v.x, v.y);
        __half2 h1 = __floats2half2_rn(v.z, v.w);
        uint2 pack = make_uint2(*(uint32_t*)&h0, *(uint32_t*)&h1);
        *(uint2*)dst = pack;
    }
}

// ===========================================================================
// HMMA GEMM (fp16, K=1024).
// ===========================================================================
template<bool QKV>
__global__ __launch_bounds__(256) void gemm_mma_kernel(
    const __half* __restrict__ A, const __half* __restrict__ Bw,
    const float* __restrict__ Rsd, float* __restrict__ C, int N)
{
    __shared__ __align__(128) __half sA[2][128*40];
    __shared__ __align__(128) __half sB[2][128*40];

    pdl_wait();

    int tid = threadIdx.x, lid = tid & 31, wid = tid >> 5;
    int wm = (wid & 1) * 64;
    int wn = (wid >> 1) * 32;
    int m0 = blockIdx.y * 128, n0 = blockIdx.x * 128;

    int ldrow = tid >> 1;
    int ldcol = (tid & 1) * 32;       // bytes
    const char* gA = (const char*)(A  + (size_t)(m0 + ldrow) * KD) + ldcol;
    const char* gB = (const char*)(Bw + (size_t)(n0 + ldrow) * KD) + ldcol;

    auto prefetch = [&](int c) {
        int s = c & 1;
        uint32_t da = smem_u32(&sA[s][ldrow * 40]) + (uint32_t)ldcol;
        uint32_t db = smem_u32(&sB[s][ldrow * 40]) + (uint32_t)ldcol;
        const char* a = gA + (size_t)c * 64;
        const char* b = gB + (size_t)c * 64;
        cp16(da, a);      cp16(da + 16, a + 16);
        cp16(db, b);      cp16(db + 16, b + 16);
        cp_commit();
    };

    float acc[4][4][4] = {};

    prefetch(0); prefetch(1);

    int g  = lid >> 3, r8 = lid & 7;
    int a_m = wm + (g & 1) * 8 + r8;
    int a_k = (g >> 1) * 8;
    int b_n = wn + (g >> 1) * 8 + r8;
    int b_k = (g & 1) * 8;

    for (int kt = 0; kt < NK; kt++) {
        int s = kt & 1;
        if (kt + 1 < NK) cp_wait<1>(); else cp_wait<0>();
        __syncthreads();

        uint32_t baseA = smem_u32(&sA[s][0]);
        uint32_t baseB = smem_u32(&sB[s][0]);
#pragma unroll
        for (int ks = 0; ks < 2; ks++) {
            uint32_t a[4][4], b[4][2];
#pragma unroll
            for (int mt = 0; mt < 4; mt++) {
                uint32_t addr = baseA + (uint32_t)(a_m + mt*16) * 80u
                                      + (uint32_t)(a_k + ks*16) * 2u;
                ldsm4(a[mt][0], a[mt][1], a[mt][2], a[mt][3], addr);
            }
#pragma unroll
            for (int nt = 0; nt < 2; nt++) {
                uint32_t r0, r1, r2, r3;
                uint32_t addr = baseB + (uint32_t)(b_n + nt*16) * 80u
                                      + (uint32_t)(b_k + ks*16) * 2u;
                ldsm4(r0, r1, r2, r3, addr);
                b[nt*2][0] = r0;   b[nt*2][1] = r1;
                b[nt*2+1][0] = r2; b[nt*2+1][1] = r3;
            }
#pragma unroll
            for (int mt = 0; mt < 4; mt++)
#pragma unroll
                for (int nn = 0; nn < 4; nn++)
                    mma16816(acc[mt][nn], a[mt], b[nn]);
        }
        __syncthreads();
        if (kt + 2 < NK) prefetch(kt + 2);
    }

    int row = lid >> 2, col = (lid & 3) * 2;
#pragma unroll
    for (int mt = 0; mt < 4; mt++) {
#pragma unroll
        for (int nn = 0; nn < 4; nn++) {
            int m = m0 + wm + mt*16 + row;
            int n = n0 + wn + nn*8 + col;
            if (QKV) {
                int sc = n >> 10, h = (n >> 6) & 15, d = n & 63;
                int t = m & (SEQ - 1), bb = m >> 11;
                size_t base = (size_t)sc * SEC_ELEMS
                            + ((size_t)(bb * NHEADS + h) * SEQ + t) * HDIM + d;
                __half2 v0 = __floats2half2_rn(acc[mt][nn][0], acc[mt][nn][1]);
                __half2 v1 = __floats2half2_rn(acc[mt][nn][2], acc[mt][nn][3]);
                *(__half2*)(g_split + base)            = v0;
                *(__half2*)(g_split + base + 8*HDIM)   = v1;
            } else {
                float2 v0 = make_float2(acc[mt][nn][0], acc[mt][nn][1]);
                float2 v1 = make_float2(acc[mt][nn][2], acc[mt][nn][3]);
                float2 q0 = *(const float2*)(Rsd + (size_t)m * N + n);
                float2 q1 = *(const float2*)(Rsd + (size_t)(m+8) * N + n);
                v0.x += q0.x; v0.y += q0.y;
                v1.x += q1.x; v1.y += q1.y;
                *(float2*)(C + (size_t)m * N + n)     = v0;
                *(float2*)(C + (size_t)(m+8) * N + n) = v1;
            }
        }
    }
}

// ===========================================================================
// K3: in-place fp16 RoPE on Q,K sections of g_split.
// ===========================================================================
__global__ void rope_kernel() {
    pdl_wait();
    int idx = blockIdx.x * 256 + threadIdx.x;   // BH*2*SEQ*16
    int k  = idx & 15;
    int t  = (idx >> 4) & (SEQ - 1);
    int sc = (idx >> 15) & 1;                   // 0 = q, 1 = k
    int bh = idx >> 16;
    __half* p = g_split + (size_t)sc * SEC_ELEMS + ((size_t)bh * SEQ + t) * HDIM + 2*k;
    float2 a = __half22float2(*(__half2*)(p));
    float2 b = __half22float2(*(__half2*)(p + 32));
    const float NEG_L2_10K_32 = -0.41524101186092029f;   // -log2(10000)/32
    float if0 = exp2f((float)(2*k)   * NEG_L2_10K_32);
    float if1 = exp2f((float)(2*k+1) * NEG_L2_10K_32);
    float s0, c0, s1, c1;
    __sincosf((float)t * if0, &s0, &c0);
    __sincosf((float)t * if1, &s1, &c1);
    float y0 = a.x*c0 - b.x*s0, y1 = a.y*c1 - b.y*s1;
    float z0 = b.x*c0 + a.x*s0, z1 = b.y*c1 + a.y*s1;
    if (sc == 0) {
        const float QS = 0.125f * 1.4426950408889634f;   // 1/sqrt(64) * log2(e)
        y0 *= QS; y1 *= QS; z0 *= QS; z1 *= QS;
    }
    *(__half2*)(p)      = __floats2half2_rn(y0, y1);
    *(__half2*)(p + 32) = __floats2half2_rn(z0, z1);
}

// ===========================================================================
// K4: HMMA causal flash attention with split-KV load balancing.
// grid.x = 48: bx<32 -> split CTA (qt = 31 - bx/2, part = bx&1, <=16 tiles);
// bx>=32 -> normal CTA (qt = 47 - bx, 0..15). Partials -> g_po/g_pml.
// SW128 tiles, 5 CTA/SM, single barrier per tile, f16x2 exp softmax.
// ===========================================================================
#define TILE_B 8192
#define ATT_SMEM (5 * TILE_B)            // 40960 bytes

__global__ __launch_bounds__(128, 5) void attn_mma_kernel() {
    extern __shared__ __half sh[];
    uint32_t bQ = smem_u32(sh);

    pdl_wait();

    int bx = blockIdx.x;
    int qt, t0, t1, part;
    bool splitout;
    if (bx < 32) {
        qt = 31 - (bx >> 1);
        part = bx & 1;
        splitout = true;
        int nt = qt + 1, half = nt >> 1;
        t0 = part ? half : 0;
        t1 = part ? nt : half;
    } else {
        qt = 47 - bx;            // 15..0
        part = 0;
        splitout = false;
        t0 = 0; t1 = qt + 1;
    }
    int hh = blockIdx.y, b = blockIdx.z;
    int bh = b * NHEADS + hh;
    int tid = threadIdx.x;
    int lid = tid & 31, wid = tid >> 5;
    int q0 = qt * 64;

    const __half* gq = g_split + 0*SEC_ELEMS + (size_t)bh * SEQ * HDIM;
    const __half* gk = g_split + 1*SEC_ELEMS + (size_t)bh * SEQ * HDIM;
    const __half* gv = g_split + 2*SEC_ELEMS + (size_t)bh * SEQ * HDIM;

    int ldrow = tid >> 1;
    int ldh   = (tid & 1) * 32;

    // Q load (joins group of first prefetch)
    {
        const __half* s0 = gq + (size_t)(q0 + ldrow) * HDIM + ldh;
#pragma unroll
        for (int i = 0; i < 4; i++) {
            uint32_t off = (uint32_t)ldrow * 128u + (uint32_t)ldh * 2u + i * 16u;
            cp16(bQ + swz(off), s0 + i*8);
        }
    }

    auto prefetch = [&](int kt) {
        int s = kt & 1;
        uint32_t baseK = bQ + (1 + s*2) * TILE_B;
        size_t gr = (size_t)(kt * 64 + ldrow) * HDIM + ldh;
        const __half* srcs[2] = { gk + gr, gv + gr };
#pragma unroll
        for (int a = 0; a < 2; a++) {
            uint32_t base = baseK + a * TILE_B;
#pragma unroll
            for (int i = 0; i < 4; i++) {
                uint32_t off = (uint32_t)ldrow * 128u + (uint32_t)ldh * 2u + i * 16u;
                cp16(base + swz(off), srcs[a] + i*8);
            }
        }
        cp_commit();
    };
    prefetch(t0);
    cp_wait<0>();
    __syncthreads();

    int g  = lid >> 3, r8 = lid & 7;
    int a_row = wid * 16 + (g & 1) * 8 + r8;
    int a_kb  = ((g >> 1) * 8) * 2;
    int b_row = (g >> 1) * 8 + r8;
    int b_kb  = ((g & 1) * 8) * 2;
    int v_row = lid & 15;
    int v_cb  = ((lid >> 4) * 8) * 2;
    int qrow_loc = wid * 16 + (lid >> 2);

    float m0 = -1e30f, m1 = -1e30f, l0 = 0.f, l1 = 0.f;
    float oacc[8][4] = {};

    for (int kt = t0; kt < t1; kt++) {
        if (kt + 1 < t1) prefetch(kt + 1);

        uint32_t bKh = bQ + (1 + (kt & 1)*2) * TILE_B;
        uint32_t bVh = bKh + TILE_B;

        // ---- S = Q K^T ----
        float sacc[8][4] = {};
#pragma unroll
        for (int kc = 0; kc < 4; kc++) {
            uint32_t ah[4];
            {
                uint32_t off = (uint32_t)a_row * 128u + (uint32_t)(kc*32 + a_kb);
                ldsm4(ah[0], ah[1], ah[2], ah[3], bQ + swz(off));
            }
            uint32_t bhf[8][2];
#pragma unroll
            for (int p = 0; p < 4; p++) {
                uint32_t off = (uint32_t)(p*16 + b_row) * 128u + (uint32_t)(kc*32 + b_kb);
                uint32_t r0, r1, r2, r3;
                ldsm4(r0, r1, r2, r3, bKh + swz(off));
                bhf[2*p][0] = r0; bhf[2*p][1] = r1;
                bhf[2*p+1][0] = r2; bhf[2*p+1][1] = r3;
            }
#pragma unroll
            for (int j = 0; j < 8; j++)
                mma16816(sacc[j], ah, bhf[j]);
        }

        // ---- causal mask on diagonal tile ----
        if (kt == qt) {
#pragma unroll
            for (int j = 0; j < 8; j++) {
                int col = j*8 + (lid & 3) * 2;
                if (col     > qrow_loc)     sacc[j][0] = -1e30f;
                if (col + 1 > qrow_loc)     sacc[j][1] = -1e30f;
                if (col     > qrow_loc + 8) sacc[j][2] = -1e30f;
                if (col + 1 > qrow_loc + 8) sacc[j][3] = -1e30f;
            }
        }

        // ---- online softmax (exp2 domain) ----
        float mx0 = -1e30f, mx1 = -1e30f;
#pragma unroll
        for (int j = 0; j < 8; j++) {
            mx0 = fmaxf(mx0, fmaxf(sacc[j][0], sacc[j][1]));
            mx1 = fmaxf(mx1, fmaxf(sacc[j][2], sacc[j][3]));
        }
        mx0 = fmaxf(mx0, __shfl_xor_sync(0xffffffffu, mx0, 1));
        mx0 = fmaxf(mx0, __shfl_xor_sync(0xffffffffu, mx0, 2));
        mx1 = fmaxf(mx1, __shfl_xor_sync(0xffffffffu, mx1, 1));
        mx1 = fmaxf(mx1, __shfl_xor_sync(0xffffffffu, mx1, 2));
        float mn0 = fmaxf(m0, mx0), mn1 = fmaxf(m1, mx1);
        float al0 = exp2f(m0 - mn0), al1 = exp2f(m1 - mn1);

        uint32_t p01[8], p23[8];
#pragma unroll
        for (int j = 0; j < 8; j++) {
            p01[j] = h2exp2(h2pack(sacc[j][0] - mn0, sacc[j][1] - mn0));
            p23[j] = h2exp2(h2pack(sacc[j][2] - mn1, sacc[j][3] - mn1));
        }
        uint32_t t01 = h2add(h2add(h2add(p01[0], p01[1]), h2add(p01[2], p01[3])),
                             h2add(h2add(p01[4], p01[5]), h2add(p01[6], p01[7])));
        uint32_t t23 = h2add(h2add(h2add(p23[0], p23[1]), h2add(p23[2], p23[3])),
                             h2add(h2add(p23[4], p23[5]), h2add(p23[6], p23[7])));
        float2 f01 = __half22float2(*(__half2*)&t01);
        float2 f23 = __half22float2(*(__half2*)&t23);
        float s0 = f01.x + f01.y;
        float s1 = f23.x + f23.y;
        s0 += __shfl_xor_sync(0xffffffffu, s0, 1);
        s0 += __shfl_xor_sync(0xffffffffu, s0, 2);
        s1 += __shfl_xor_sync(0xffffffffu, s1, 1);
        s1 += __shfl_xor_sync(0xffffffffu, s1, 2);
        l0 = l0 * al0 + s0;  l1 = l1 * al1 + s1;
        m0 = mn0;  m1 = mn1;
#pragma unroll
        for (int j = 0; j < 8; j++) {
            oacc[j][0] *= al0; oacc[j][1] *= al0;
            oacc[j][2] *= al1; oacc[j][3] *= al1;
        }

        // ---- O += P V ----
#pragma unroll
        for (int kc = 0; kc < 4; kc++) {
            uint32_t aH[4] = { p01[2*kc], p23[2*kc], p01[2*kc+1], p23[2*kc+1] };
#pragma unroll
            for (int p = 0; p < 4; p++) {
                uint32_t off = (uint32_t)(kc*16 + v_row) * 128u + (uint32_t)(p*32 + v_cb);
                uint32_t h0, h1, h2, h3;
                ldsm4t(h0, h1, h2, h3, bVh + swz(off));
                uint32_t bv0[2] = { h0, h1 }, bv1[2] = { h2, h3 };
                mma16816(oacc[2*p],   aH, bv0);
                mma16816(oacc[2*p+1], aH, bv1);
            }
        }

        if (kt + 1 < t1) {
            cp_wait<0>();
            __syncthreads();
        }
    }

    // ---- epilogue ----
    if (splitout) {
        // unnormalized partials + (m,l) to scratch
        size_t pb = (size_t)part * PO_STRIDE
                  + ((size_t)(bh * 16 + (qt - 16)) * 64) * 64;
#pragma unroll
        for (int j = 0; j < 8; j++) {
            int col = j*8 + (lid & 3) * 2;
            *(float2*)(g_po + pb + (size_t)qrow_loc * 64 + col)
                = make_float2(oacc[j][0], oacc[j][1]);
            *(float2*)(g_po + pb + (size_t)(qrow_loc + 8) * 64 + col)
                = make_float2(oacc[j][2], oacc[j][3]);
        }
        if ((lid & 3) == 0) {
            size_t mb = (size_t)part * (BH*16*64) + (size_t)(bh * 16 + (qt - 16)) * 64;
            g_pml[mb + qrow_loc]     = make_float2(m0, l0);
            g_pml[mb + qrow_loc + 8] = make_float2(m1, l1);
        }
    } else {
        float inv0 = 1.0f / l0, inv1 = 1.0f / l1;
        int mg0 = b * SEQ + q0 + qrow_loc;
        int mg1 = mg0 + 8;
#pragma unroll
        for (int j = 0; j < 8; j++) {
            int col = hh * HDIM + j*8 + (lid & 3) * 2;
            __half2 hp0 = __floats2half2_rn(oacc[j][0] * inv0, oacc[j][1] * inv0);
            __half2 hp1 = __floats2half2_rn(oacc[j][2] * inv1, oacc[j][3] * inv1);
            *(__half2*)(g_abf + (size_t)mg0 * KD + col) = hp0;
            *(__half2*)(g_abf + (size_t)mg1 * KD + col) = hp1;
        }
    }
}

// ===========================================================================
// K5: combine split-KV partials -> g_abf (fp16).
// One thread per (bh, q16, row, dimpair): 1,048,576 threads.
// ===========================================================================
__global__ void combine_kernel() {
    pdl_wait();
    int idx = blockIdx.x * 256 + threadIdx.x;
    int dp  = idx & 31;
    int row = (idx >> 5) & 63;
    int q16 = (idx >> 11) & 15;
    int bh  = idx >> 15;

    size_t rbase = ((size_t)(bh * 16 + q16) * 64 + row);
    size_t obase = rbase * 64 + dp * 2;
    float2 oa = *(const float2*)(g_po + obase);
    float2 ob = *(const float2*)(g_po + PO_STRIDE + obase);
    float2 mla = g_pml[rbase];
    float2 mlb = g_pml[(size_t)BH*16*64 + rbase];

    float M  = fmaxf(mla.x, mlb.x);
    float wa = exp2f(mla.x - M), wb = exp2f(mlb.x - M);
    float invl = 1.0f / (mla.y * wa + mlb.y * wb);
    float o0 = (oa.x * wa + ob.x * wb) * invl;
    float o1 = (oa.y * wa + ob.y * wb) * invl;

    int qt = 16 + q16;
    int b = bh >> 4, hh = bh & 15;
    int mg = b * SEQ + qt * 64 + row;
    int col = hh * HDIM + dp * 2;
    *(__half2*)(g_abf + (size_t)mg * KD + col) = __floats2half2_rn(o0, o1);
}

// ===========================================================================
extern "C" void kernel_launch(void* const* d_in, const int* in_sizes, int n_in,
                              void* d_out, int out_size) {
    const float* x      = (const float*)d_in[0];
    const float* norm_w = (const float*)d_in[1];
    const float* w_qkv  = (const float*)d_in[2];
    const float* w_out  = (const float*)d_in[3];
    float* out = (float*)d_out;

    __half *p_abf, *p_bbf, *p_bbf2;
    cudaGetSymbolAddress((void**)&p_abf,  g_abf);
    cudaGetSymbolAddress((void**)&p_bbf,  g_bbf);
    cudaGetSymbolAddress((void**)&p_bbf2, g_bbf2);

    cudaFuncSetAttribute(attn_mma_kernel,
                         cudaFuncAttributeMaxDynamicSharedMemorySize, ATT_SMEM);

    cudaLaunchAttribute pdl[1];
    pdl[0].id = cudaLaunchAttributeProgrammaticStreamSerialization;
    pdl[0].val.programmaticStreamSerializationAllowed = 1;

    // 1. merged RMSNorm + weight convert
    prep_kernel<<<MROWS + ((EDIM+DMODEL)*DMODEL)/(256*4), 256>>>(x, norm_w, w_qkv, w_out);

    // 2. QKV projection
    {
        cudaLaunchConfig_t cfg = {};
        cfg.gridDim = dim3(EDIM/128, MROWS/128);
        cfg.blockDim = dim3(256);
        cfg.attrs = pdl; cfg.numAttrs = 1;
        cudaLaunchKernelEx(&cfg, gemm_mma_kernel<true>,
                           (const __half*)p_abf, (const __half*)p_bbf,
                           (const float*)nullptr, (float*)nullptr, (int)EDIM);
    }

    // 3. RoPE
    {
        cudaLaunchConfig_t cfg = {};
        cfg.gridDim = dim3((BH * 2 * SEQ * 16) / 256);
        cfg.blockDim = dim3(256);
        cfg.attrs = pdl; cfg.numAttrs = 1;
        cudaLaunchKernelEx(&cfg, rope_kernel);
    }

    // 4. attention (split-KV load-balanced, 48 x 16 x 2 grid)
    {
        cudaLaunchConfig_t cfg = {};
        cfg.gridDim = dim3(48, NHEADS, BATCH);
        cfg.blockDim = dim3(128);
        cfg.dynamicSmemBytes = ATT_SMEM;
        cfg.attrs = pdl; cfg.numAttrs = 1;
        cudaLaunchKernelEx(&cfg, attn_mma_kernel);
    }

    // 5. combine split partials
    {
        cudaLaunchConfig_t cfg = {};
        cfg.gridDim = dim3((BH * 16 * 64 * 32) / 256);
        cfg.blockDim = dim3(256);
        cfg.attrs = pdl; cfg.numAttrs = 1;
        cudaLaunchKernelEx(&cfg, combine_kernel);
    }

    // 6. Output projection + residual
    {
        cudaLaunchConfig_t cfg = {};
        cfg.gridDim = dim3(DMODEL/128, MROWS/128);
        cfg.blockDim = dim3(256);
        cfg.attrs = pdl; cfg.numAttrs = 1;
        cudaLaunchKernelEx(&cfg, gemm_mma_kernel<false>,
                           (const __half*)p_abf, (const __half*)p_bbf2,
                           (const float*)x, (float*)out, (int)DMODEL);
    }
}